// round 12
// baseline (speedup 1.0000x reference)
#include <cuda_runtime.h>
#include <cuda_bf16.h>
#include <math_constants.h>
#include <cstdint>

// Problem constants
#define NN      50000
#define NPAD    50048       // MT64 * 64
#define EE      400000
#define EP      450000      // E + N self loops
#define D_IN    6
#define HID     128
#define NH      4
#define HC      512         // NH * 128
#define LL      3
#define NHYP    4096
#define MT64    782         // ceil(NN/64)
#define SCAN_BLOCKS 49

// ---------------- device scratch (static, no allocation) ----------------
__device__ float g_hbuf[2][NN * HID];        // ping-pong node features
__device__ float g_asb [2][NN * NH];         // ping-pong attn dots
__device__ float g_adb [2][NN * NH];
__device__ __nv_bfloat16 g_a_hi[NPAD * HID]; // encoder GEMM A operand (split)
__device__ __nv_bfloat16 g_a_lo[NPAD * HID];
__device__ float g_was[LL * HC];
__device__ float g_wad[LL * HC];
__device__ int   g_cnt   [NN];
__device__ int   g_rowptr[NN + 1];
__device__ int   g_cursor[NN];
__device__ int   g_srcs  [EP];
__device__ int   g_bsum  [64];
__device__ __nv_bfloat16 g_wt_hi [LL * HC * HID];  // layer Wcat^T split: [l][c*512 + k]
__device__ __nv_bfloat16 g_wt_lo [LL * HC * HID];
__device__ __nv_bfloat16 g_wte_hi[HID * HID];      // encoder W2^T split [128,128]
__device__ __nv_bfloat16 g_wte_lo[HID * HID];

// ---------------- helpers ----------------
__device__ __forceinline__ uint32_t smem_u32(const void* p) {
    uint32_t a;
    asm("{ .reg .u64 t; cvta.to.shared.u64 t, %1; cvt.u32.u64 %0, t; }" : "=r"(a) : "l"(p));
    return a;
}
__device__ __forceinline__ void ldsm_x4(uint32_t& a0, uint32_t& a1, uint32_t& a2, uint32_t& a3, uint32_t addr) {
    asm volatile("ldmatrix.sync.aligned.m8n8.x4.shared.b16 {%0,%1,%2,%3}, [%4];"
                 : "=r"(a0), "=r"(a1), "=r"(a2), "=r"(a3) : "r"(addr));
}
__device__ __forceinline__ void mma16816(float* c, const uint32_t* a, uint32_t b0, uint32_t b1) {
    asm volatile("mma.sync.aligned.m16n8k16.row.col.f32.bf16.bf16.f32 "
                 "{%0,%1,%2,%3}, {%4,%5,%6,%7}, {%8,%9}, {%0,%1,%2,%3};"
                 : "+f"(c[0]), "+f"(c[1]), "+f"(c[2]), "+f"(c[3])
                 : "r"(a[0]), "r"(a[1]), "r"(a[2]), "r"(a[3]), "r"(b0), "r"(b1));
}
#define CP_ASYNC16(dst, src) asm volatile("cp.async.cg.shared.global [%0], [%1], 16;" :: "r"(dst), "l"(src))
#define CP_COMMIT()          asm volatile("cp.async.commit_group;" ::: "memory")
#define CP_WAIT0()           asm volatile("cp.async.wait_group 0;" ::: "memory")

__device__ __forceinline__ void split_bf16(float v, __nv_bfloat16& h, __nv_bfloat16& l) {
    h = __float2bfloat16(v);
    l = __float2bfloat16(v - __bfloat162float(h));
}

// smem layout constants
#define ROWB  272
#define ATILE (64 * ROWB)            // 17408
#define BTILE (128 * ROWB)           // 34816
// encoder gemm (K=128): A hi/lo + B hi/lo single stage
#define OFF_AHI 0
#define OFF_ALO ATILE
#define OFF_BHI (2 * ATILE)
#define OFF_BLO (2 * ATILE + BTILE)
#define ENC_SMEM (2 * ATILE + 2 * BTILE)   // 104448 -> 2 CTAs/SM
// fused layer kernel (K=512): z 4 chunks x (hi+lo) + B single chunk (hi+lo)
#define OFF_Z   0
#define ZCH(ch) (OFF_Z + (ch) * 2 * ATILE)  // hi at +0, lo at +ATILE
#define OFF_B   (8 * ATILE)                 // 139264
#define LAY_SMEM (8 * ATILE + 2 * BTILE)    // 208896 -> 1 CTA/SM
#define CS_STRIDE 133

// ================= encoder tensor-core GEMM (K=128) + dots epilogue =================
__global__ __launch_bounds__(256) void gemm2(
        const __nv_bfloat16* __restrict__ A_hi, const __nv_bfloat16* __restrict__ A_lo,
        const __nv_bfloat16* __restrict__ Bt_hi, const __nv_bfloat16* __restrict__ Bt_lo,
        const float* __restrict__ bias,
        const float* __restrict__ was, const float* __restrict__ wad,
        float* __restrict__ Cout,
        float* __restrict__ as_out, float* __restrict__ ad_out, int M) {
    extern __shared__ char smem[];
    __shared__ float s_was[HC], s_wad[HC];
    __shared__ float s_bias[128];
    const uint32_t sb = smem_u32(smem);
    const int tid = threadIdx.x, wid = tid >> 5, lane = tid & 31;
    const int rowBase = blockIdx.x * 64;

    if (tid < 128) s_bias[tid] = bias[tid];
    for (int i = tid; i < HC; i += 256) { s_was[i] = was[i]; s_wad[i] = wad[i]; }

    const int wm = wid & 1, wn = wid >> 1;
    const int mW = wm * 32, nW = wn * 32;
    float acc[2][4][4];
    #pragma unroll
    for (int mi = 0; mi < 2; mi++)
        #pragma unroll
        for (int ni = 0; ni < 4; ni++)
            #pragma unroll
            for (int j = 0; j < 4; j++) acc[mi][ni][j] = 0.f;

    const int aRow  = (lane & 15);
    const int aColB = ((lane >> 4) & 1) * 16;
    const int bRow  = ((lane >> 4) & 1) * 8 + (lane & 7);
    const int bColB = ((lane >> 3) & 1) * 16;
    const uint32_t aHi = sb + OFF_AHI, aLo = sb + OFF_ALO;
    const uint32_t bHi = sb + OFF_BHI, bLo = sb + OFF_BLO;

    // single K=128 chunk
    #pragma unroll
    for (int i = 0; i < 8; i++) {
        int li = tid + 256 * i;
        int row = li >> 4, c8 = (li & 15) * 8;
        size_t gidx = (size_t)row * HID + c8;
        uint32_t off = (uint32_t)row * ROWB + (uint32_t)c8 * 2;
        CP_ASYNC16(sb + OFF_BHI + off, &Bt_hi[gidx]);
        CP_ASYNC16(sb + OFF_BLO + off, &Bt_lo[gidx]);
    }
    #pragma unroll
    for (int i = 0; i < 4; i++) {
        int li = tid + 256 * i;
        int row = li >> 4, c8 = (li & 15) * 8;
        size_t gidx = (size_t)(rowBase + row) * HID + c8;
        uint32_t off = (uint32_t)row * ROWB + (uint32_t)c8 * 2;
        CP_ASYNC16(sb + OFF_AHI + off, &A_hi[gidx]);
        CP_ASYNC16(sb + OFF_ALO + off, &A_lo[gidx]);
    }
    CP_COMMIT();
    CP_WAIT0();
    __syncthreads();

    #pragma unroll
    for (int kb = 0; kb < 8; kb++) {
        const uint32_t kByte = kb * 32;
        uint32_t ah[2][4], al[2][4], bh[4][2], bl[4][2];
        #pragma unroll
        for (int mi = 0; mi < 2; mi++) {
            uint32_t ao = (uint32_t)(mW + mi * 16 + aRow) * ROWB + kByte + aColB;
            ldsm_x4(ah[mi][0], ah[mi][1], ah[mi][2], ah[mi][3], aHi + ao);
            ldsm_x4(al[mi][0], al[mi][1], al[mi][2], al[mi][3], aLo + ao);
        }
        #pragma unroll
        for (int nj = 0; nj < 2; nj++) {
            uint32_t bo = (uint32_t)(nW + nj * 16 + bRow) * ROWB + kByte + bColB;
            ldsm_x4(bh[nj*2][0], bh[nj*2][1], bh[nj*2+1][0], bh[nj*2+1][1], bHi + bo);
            ldsm_x4(bl[nj*2][0], bl[nj*2][1], bl[nj*2+1][0], bl[nj*2+1][1], bLo + bo);
        }
        #pragma unroll
        for (int mi = 0; mi < 2; mi++)
            #pragma unroll
            for (int ni = 0; ni < 4; ni++) {
                mma16816(acc[mi][ni], ah[mi], bh[ni][0], bh[ni][1]);
                mma16816(acc[mi][ni], ah[mi], bl[ni][0], bl[ni][1]);
                mma16816(acc[mi][ni], al[mi], bh[ni][0], bh[ni][1]);
            }
    }
    __syncthreads();

    float* cs = (float*)smem;
    {
        const int r0 = (lane >> 2), c0 = (lane & 3) * 2;
        #pragma unroll
        for (int mi = 0; mi < 2; mi++)
            #pragma unroll
            for (int ni = 0; ni < 4; ni++) {
                int rr = mW + mi * 16 + r0;
                int cc = nW + ni * 8 + c0;
                cs[rr * CS_STRIDE + cc]           = acc[mi][ni][0];
                cs[rr * CS_STRIDE + cc + 1]       = acc[mi][ni][1];
                cs[(rr + 8) * CS_STRIDE + cc]     = acc[mi][ni][2];
                cs[(rr + 8) * CS_STRIDE + cc + 1] = acc[mi][ni][3];
            }
    }
    __syncthreads();

    #pragma unroll
    for (int i = 0; i < 8; i++) {
        int li = tid + 256 * i;
        int row = li >> 5, c4 = (li & 31) * 4;
        int gr = rowBase + row;
        float y0 = cs[row * CS_STRIDE + c4 + 0] + s_bias[c4 + 0];
        float y1 = cs[row * CS_STRIDE + c4 + 1] + s_bias[c4 + 1];
        float y2 = cs[row * CS_STRIDE + c4 + 2] + s_bias[c4 + 2];
        float y3 = cs[row * CS_STRIDE + c4 + 3] + s_bias[c4 + 3];
        cs[row * CS_STRIDE + c4 + 0] = y0;
        cs[row * CS_STRIDE + c4 + 1] = y1;
        cs[row * CS_STRIDE + c4 + 2] = y2;
        cs[row * CS_STRIDE + c4 + 3] = y3;
        if (gr < M)
            *(float4*)&Cout[(size_t)gr * HID + c4] = make_float4(y0, y1, y2, y3);
    }
    __syncthreads();

    if (tid < 128) {
        int row = tid >> 1, cb = (tid & 1) * 64;
        int gr = rowBase + row;
        float as[4] = {0, 0, 0, 0}, ad[4] = {0, 0, 0, 0};
        const float* cr = cs + row * CS_STRIDE;
        #pragma unroll 4
        for (int c = cb; c < cb + 64; c++) {
            float y = cr[c];
            #pragma unroll
            for (int h = 0; h < 4; h++) {
                as[h] += y * s_was[h * 128 + c];
                ad[h] += y * s_wad[h * 128 + c];
            }
        }
        #pragma unroll
        for (int h = 0; h < 4; h++) {
            as[h] += __shfl_down_sync(0xFFFFFFFF, as[h], 1);
            ad[h] += __shfl_down_sync(0xFFFFFFFF, ad[h], 1);
        }
        if (((tid & 1) == 0) && gr < M) {
            #pragma unroll
            for (int h = 0; h < 4; h++) {
                as_out[gr * 4 + h] = as[h];
                ad_out[gr * 4 + h] = ad[h];
            }
        }
    }
}

// ================= fused layer kernel: aggregation -> GEMM(K=512) -> epilogue =================
__global__ __launch_bounds__(256) void k_layer(
        const __nv_bfloat16* __restrict__ Bt_hi, const __nv_bfloat16* __restrict__ Bt_lo,
        const float* __restrict__ bias,
        const float* __restrict__ lng, const float* __restrict__ lnb,
        const float* __restrict__ was, const float* __restrict__ wad,   // next-layer dot weights (nullable)
        const float* __restrict__ h_in, float* __restrict__ h_out,
        const float* __restrict__ as_in, const float* __restrict__ ad_in,
        float* __restrict__ as_out, float* __restrict__ ad_out) {
    extern __shared__ char smem[];
    __shared__ float s_was[HC], s_wad[HC];
    __shared__ float s_bias[128], s_lng[128], s_lnb[128];
    __shared__ float s_mu[64], s_rstd[64];
    const uint32_t sb = smem_u32(smem);
    const int tid = threadIdx.x, wid = tid >> 5, lane = tid & 31;
    const int rowBase = blockIdx.x * 64;
    const bool dots = (was != nullptr);

    if (tid < 128) { s_bias[tid] = bias[tid]; s_lng[tid] = lng[tid]; s_lnb[tid] = lnb[tid]; }
    if (dots)
        for (int i = tid; i < HC; i += 256) { s_was[i] = was[i]; s_wad[i] = wad[i]; }

    // ---- B chunk loader ----
    auto load_B = [&](int ch) {
        #pragma unroll
        for (int i = 0; i < 8; i++) {
            int li = tid + 256 * i;
            int row = li >> 4, c8 = (li & 15) * 8;
            size_t gidx = (size_t)row * HC + ch * 128 + c8;
            uint32_t off = (uint32_t)row * ROWB + (uint32_t)c8 * 2;
            CP_ASYNC16(sb + OFF_B + off, &Bt_hi[gidx]);
            CP_ASYNC16(sb + OFF_B + BTILE + off, &Bt_lo[gidx]);
        }
        CP_COMMIT();
    };

    // prefetch B chunk 0 under the aggregation phase
    load_B(0);

    // ---- phase 1: aggregation (warp per node, 8 iterations) -> z in smem ----
    for (int it = 0; it < 8; it++) {
        int row = it * 8 + wid;
        int n = rowBase + row;
        if (n < NN) {
            int r0 = g_rowptr[n], r1 = g_rowptr[n + 1];
            float4 adv = *(const float4*)&ad_in[n * 4];
            float adh[4] = {adv.x, adv.y, adv.z, adv.w};

            float m[4] = {-CUDART_INF_F, -CUDART_INF_F, -CUDART_INF_F, -CUDART_INF_F};
            for (int idx = r0 + lane; idx < r1; idx += 32) {
                int s = g_srcs[idx];
                float4 asv = *(const float4*)&as_in[s * 4];
                float e0 = asv.x + adh[0]; e0 = e0 > 0 ? e0 : 0.2f * e0; m[0] = fmaxf(m[0], e0);
                float e1 = asv.y + adh[1]; e1 = e1 > 0 ? e1 : 0.2f * e1; m[1] = fmaxf(m[1], e1);
                float e2 = asv.z + adh[2]; e2 = e2 > 0 ? e2 : 0.2f * e2; m[2] = fmaxf(m[2], e2);
                float e3 = asv.w + adh[3]; e3 = e3 > 0 ? e3 : 0.2f * e3; m[3] = fmaxf(m[3], e3);
            }
            #pragma unroll
            for (int off = 16; off; off >>= 1)
                #pragma unroll
                for (int h = 0; h < 4; h++)
                    m[h] = fmaxf(m[h], __shfl_xor_sync(0xFFFFFFFF, m[h], off));

            float denom[4] = {0, 0, 0, 0};
            float z[4][4];
            #pragma unroll
            for (int h = 0; h < 4; h++)
                #pragma unroll
                for (int i = 0; i < 4; i++) z[h][i] = 0.f;

            for (int idx = r0; idx < r1; idx++) {
                int s = g_srcs[idx];
                float4 asv = *(const float4*)&as_in[s * 4];
                float ex[4];
                {
                    float e;
                    e = asv.x + adh[0]; e = e > 0 ? e : 0.2f * e; ex[0] = __expf(e - m[0]);
                    e = asv.y + adh[1]; e = e > 0 ? e : 0.2f * e; ex[1] = __expf(e - m[1]);
                    e = asv.z + adh[2]; e = e > 0 ? e : 0.2f * e; ex[2] = __expf(e - m[2]);
                    e = asv.w + adh[3]; e = e > 0 ? e : 0.2f * e; ex[3] = __expf(e - m[3]);
                }
                denom[0] += ex[0]; denom[1] += ex[1]; denom[2] += ex[2]; denom[3] += ex[3];
                float4 hv = *(const float4*)&h_in[(size_t)s * HID + lane * 4];
                #pragma unroll
                for (int h = 0; h < 4; h++) {
                    z[h][0] += ex[h] * hv.x;
                    z[h][1] += ex[h] * hv.y;
                    z[h][2] += ex[h] * hv.z;
                    z[h][3] += ex[h] * hv.w;
                }
            }

            #pragma unroll
            for (int h = 0; h < 4; h++) {
                float inv = 1.0f / (denom[h] + 1e-16f);
                __nv_bfloat16 hi[4], lo[4];
                #pragma unroll
                for (int i = 0; i < 4; i++) split_bf16(z[h][i] * inv, hi[i], lo[i]);
                uint32_t off = (uint32_t)row * ROWB + (uint32_t)lane * 8;
                *(uint2*)(smem + ZCH(h) + off)         = *(uint2*)hi;
                *(uint2*)(smem + ZCH(h) + ATILE + off) = *(uint2*)lo;
            }
        }
    }
    CP_WAIT0();
    __syncthreads();

    // ---- phase 2: GEMM over 4 K-chunks, A resident in smem ----
    const int wm = wid & 1, wn = wid >> 1;
    const int mW = wm * 32, nW = wn * 32;
    float acc[2][4][4];
    #pragma unroll
    for (int mi = 0; mi < 2; mi++)
        #pragma unroll
        for (int ni = 0; ni < 4; ni++)
            #pragma unroll
            for (int j = 0; j < 4; j++) acc[mi][ni][j] = 0.f;

    const int aRow  = (lane & 15);
    const int aColB = ((lane >> 4) & 1) * 16;
    const int bRow  = ((lane >> 4) & 1) * 8 + (lane & 7);
    const int bColB = ((lane >> 3) & 1) * 16;
    const uint32_t bHi = sb + OFF_B, bLo = sb + OFF_B + BTILE;

    for (int ch = 0; ch < 4; ch++) {
        const uint32_t aHi = sb + ZCH(ch), aLo = aHi + ATILE;
        #pragma unroll
        for (int kb = 0; kb < 8; kb++) {
            const uint32_t kByte = kb * 32;
            uint32_t ah[2][4], al[2][4], bh[4][2], bl[4][2];
            #pragma unroll
            for (int mi = 0; mi < 2; mi++) {
                uint32_t ao = (uint32_t)(mW + mi * 16 + aRow) * ROWB + kByte + aColB;
                ldsm_x4(ah[mi][0], ah[mi][1], ah[mi][2], ah[mi][3], aHi + ao);
                ldsm_x4(al[mi][0], al[mi][1], al[mi][2], al[mi][3], aLo + ao);
            }
            #pragma unroll
            for (int nj = 0; nj < 2; nj++) {
                uint32_t bo = (uint32_t)(nW + nj * 16 + bRow) * ROWB + kByte + bColB;
                ldsm_x4(bh[nj*2][0], bh[nj*2][1], bh[nj*2+1][0], bh[nj*2+1][1], bHi + bo);
                ldsm_x4(bl[nj*2][0], bl[nj*2][1], bl[nj*2+1][0], bl[nj*2+1][1], bLo + bo);
            }
            #pragma unroll
            for (int mi = 0; mi < 2; mi++)
                #pragma unroll
                for (int ni = 0; ni < 4; ni++) {
                    mma16816(acc[mi][ni], ah[mi], bh[ni][0], bh[ni][1]);
                    mma16816(acc[mi][ni], ah[mi], bl[ni][0], bl[ni][1]);
                    mma16816(acc[mi][ni], al[mi], bh[ni][0], bh[ni][1]);
                }
        }
        if (ch < 3) {
            __syncthreads();       // all warps done reading B chunk
            load_B(ch + 1);
            CP_WAIT0();
            __syncthreads();
        }
    }
    __syncthreads();

    // ---- epilogue: 0.25*acc + bias -> LN -> relu -> +residual; dots for next layer ----
    float* cs = (float*)smem;
    {
        const int r0 = (lane >> 2), c0 = (lane & 3) * 2;
        #pragma unroll
        for (int mi = 0; mi < 2; mi++)
            #pragma unroll
            for (int ni = 0; ni < 4; ni++) {
                int rr = mW + mi * 16 + r0;
                int cc = nW + ni * 8 + c0;
                cs[rr * CS_STRIDE + cc]           = acc[mi][ni][0];
                cs[rr * CS_STRIDE + cc + 1]       = acc[mi][ni][1];
                cs[(rr + 8) * CS_STRIDE + cc]     = acc[mi][ni][2];
                cs[(rr + 8) * CS_STRIDE + cc + 1] = acc[mi][ni][3];
            }
    }
    __syncthreads();

    #pragma unroll
    for (int i = 0; i < 8; i++) {
        int li = tid + 256 * i;
        int row = li >> 5, c4 = (li & 31) * 4;
        #pragma unroll
        for (int j = 0; j < 4; j++)
            cs[row * CS_STRIDE + c4 + j] = 0.25f * cs[row * CS_STRIDE + c4 + j] + s_bias[c4 + j];
    }
    __syncthreads();
    if (tid < 64) {
        const float* cr = cs + tid * CS_STRIDE;
        float sum = 0.f;
        #pragma unroll 8
        for (int c = 0; c < 128; c++) sum += cr[c];
        float mu = sum * (1.0f / 128.0f);
        float var = 0.f;
        #pragma unroll 8
        for (int c = 0; c < 128; c++) { float d = cr[c] - mu; var += d * d; }
        s_mu[tid] = mu;
        s_rstd[tid] = rsqrtf(var * (1.0f / 128.0f) + 1e-5f);
    }
    __syncthreads();
    #pragma unroll
    for (int i = 0; i < 8; i++) {
        int li = tid + 256 * i;
        int row = li >> 5, c4 = (li & 31) * 4;
        int gr = rowBase + row;
        float mu = s_mu[row], rs = s_rstd[row];
        float y[4];
        #pragma unroll
        for (int j = 0; j < 4; j++) {
            float v = (cs[row * CS_STRIDE + c4 + j] - mu) * rs * s_lng[c4 + j] + s_lnb[c4 + j];
            y[j] = fmaxf(v, 0.f);
        }
        if (gr < NN) {
            float4 res = *(const float4*)&h_in[(size_t)gr * HID + c4];
            float4 o = make_float4(y[0] + res.x, y[1] + res.y, y[2] + res.z, y[3] + res.w);
            *(float4*)&h_out[(size_t)gr * HID + c4] = o;
            cs[row * CS_STRIDE + c4 + 0] = o.x;
            cs[row * CS_STRIDE + c4 + 1] = o.y;
            cs[row * CS_STRIDE + c4 + 2] = o.z;
            cs[row * CS_STRIDE + c4 + 3] = o.w;
        }
    }
    __syncthreads();

    if (dots && tid < 128) {
        int row = tid >> 1, cb = (tid & 1) * 64;
        int gr = rowBase + row;
        float as[4] = {0, 0, 0, 0}, ad[4] = {0, 0, 0, 0};
        const float* cr = cs + row * CS_STRIDE;
        #pragma unroll 4
        for (int c = cb; c < cb + 64; c++) {
            float y = cr[c];
            #pragma unroll
            for (int h = 0; h < 4; h++) {
                as[h] += y * s_was[h * 128 + c];
                ad[h] += y * s_wad[h * 128 + c];
            }
        }
        #pragma unroll
        for (int h = 0; h < 4; h++) {
            as[h] += __shfl_down_sync(0xFFFFFFFF, as[h], 1);
            ad[h] += __shfl_down_sync(0xFFFFFFFF, ad[h], 1);
        }
        if (((tid & 1) == 0) && gr < NN) {
            #pragma unroll
            for (int h = 0; h < 4; h++) {
                as_out[gr * 4 + h] = as[h];
                ad_out[gr * 4 + h] = ad[h];
            }
        }
    }
}

// ---------------- encoder W2 transpose+split ----------------
__global__ void k_wsplit(const float* __restrict__ W, __nv_bfloat16* __restrict__ hi,
                         __nv_bfloat16* __restrict__ lo, int NC) {
    int idx = blockIdx.x * blockDim.x + threadIdx.x;
    if (idx >= NC * 128) return;
    int n = idx >> 7, k = idx & 127;
    float x = W[k * NC + n];
    split_bf16(x, hi[idx], lo[idx]);
}

// ---------------- layer Wcat^T split ----------------
__global__ void k_wsplit_cat(const float* __restrict__ gat_W) {
    int idx = blockIdx.x * blockDim.x + threadIdx.x;
    if (idx >= LL * HC * HID) return;
    int l = idx >> 16;
    int r = idx & 65535;
    int c = r >> 9;
    int k = r & 511;
    int j = k & 127, hh = k >> 7;
    float x = gat_W[(size_t)l * 65536 + j * 512 + hh * 128 + c];
    split_bf16(x, g_wt_hi[idx], g_wt_lo[idx]);
}

// ---------------- attn weight vectors ----------------
__global__ void k_wattn(const float* __restrict__ gat_W,
                        const float* __restrict__ att_src, const float* __restrict__ att_dst) {
    int idx = blockIdx.x * blockDim.x + threadIdx.x;
    if (idx >= LL * HC) return;
    int l = idx >> 9;
    int r = idx & 511;
    int hh = r >> 7, j = r & 127;
    const float* wr = gat_W + (size_t)l * 65536 + j * 512 + hh * 128;
    const float* as = att_src + l * HC + hh * 128;
    const float* ad = att_dst + l * HC + hh * 128;
    float sa = 0.f, sd = 0.f;
    #pragma unroll 8
    for (int c = 0; c < 128; c++) { sa += wr[c] * as[c]; sd += wr[c] * ad[c]; }
    g_was[idx] = sa;
    g_wad[idx] = sd;
}

// ---------------- CSR build ----------------
__global__ void k_init_counts() {
    int n = blockIdx.x * blockDim.x + threadIdx.x;
    if (n < NN) g_cnt[n] = 1;
}
__global__ void k_count(const int* __restrict__ dst) {
    int e = blockIdx.x * blockDim.x + threadIdx.x;
    if (e < EE) atomicAdd(&g_cnt[dst[e]], 1);
}
__global__ void k_scan1() {
    __shared__ int s[1024];
    int t = threadIdx.x;
    int i = blockIdx.x * 1024 + t;
    int v = (i < NN) ? g_cnt[i] : 0;
    s[t] = v;
    __syncthreads();
    #pragma unroll
    for (int off = 1; off < 1024; off <<= 1) {
        int x = (t >= off) ? s[t - off] : 0;
        __syncthreads();
        s[t] += x;
        __syncthreads();
    }
    if (i < NN) g_rowptr[i + 1] = s[t];
    if (t == 1023) g_bsum[blockIdx.x] = s[1023];
}
__global__ void k_scan2() {
    __shared__ int s[64];
    int t = threadIdx.x;
    int v = (t < SCAN_BLOCKS) ? g_bsum[t] : 0;
    s[t] = v;
    __syncthreads();
    #pragma unroll
    for (int off = 1; off < 64; off <<= 1) {
        int x = (t >= off) ? s[t - off] : 0;
        __syncthreads();
        s[t] += x;
        __syncthreads();
    }
    if (t < SCAN_BLOCKS) g_bsum[t] = s[t] - v;   // exclusive
}
__global__ void k_scan3() {
    int t = threadIdx.x;
    int i = blockIdx.x * 1024 + t;
    if (i < NN) {
        int v = g_rowptr[i + 1] + g_bsum[blockIdx.x];
        g_rowptr[i + 1] = v;
        if (i + 1 < NN) g_cursor[i + 1] = v;
    }
    if (i == 0) { g_rowptr[0] = 0; g_cursor[0] = 0; }
}
__global__ void k_scatter(const int* __restrict__ ei) {
    int e = blockIdx.x * blockDim.x + threadIdx.x;
    if (e >= EP) return;
    int s, d;
    if (e < EE) { s = ei[e]; d = ei[EE + e]; }
    else        { s = e - EE; d = s; }
    int pos = atomicAdd(&g_cursor[d], 1);
    g_srcs[pos] = s;
}

// ---------------- encoder first layer (K=6), W1 in smem, writes split bf16 ----------------
__global__ __launch_bounds__(256) void k_enc1(const float* __restrict__ x,
                                              const float* __restrict__ W1,
                                              const float* __restrict__ b1) {
    __shared__ float sW[D_IN * HID], sB[HID];
    int tid = threadIdx.x;
    for (int i = tid; i < D_IN * HID; i += 256) sW[i] = W1[i];
    if (tid < HID) sB[tid] = b1[tid];
    __syncthreads();

    int gid = blockIdx.x * 256 + tid;
    if (gid >= NN * 32) return;
    int n = gid >> 5, c4 = (gid & 31) * 4;
    const float* xr = x + n * D_IN;
    float xv[D_IN];
    #pragma unroll
    for (int k = 0; k < D_IN; k++) xv[k] = xr[k];
    __nv_bfloat16 hi[4], lo[4];
    #pragma unroll
    for (int j = 0; j < 4; j++) {
        int c = c4 + j;
        float acc = sB[c];
        #pragma unroll
        for (int k = 0; k < D_IN; k++) acc += xv[k] * sW[k * HID + c];
        split_bf16(fmaxf(acc, 0.0f), hi[j], lo[j]);
    }
    *(uint2*)&g_a_hi[(size_t)n * HID + c4] = *(uint2*)hi;
    *(uint2*)&g_a_lo[(size_t)n * HID + c4] = *(uint2*)lo;
}

// ---------------- head MLP ----------------
__global__ __launch_bounds__(256) void k_head(const int* __restrict__ hyp,
                                              const float* __restrict__ hfin,
                                              const float* __restrict__ W1,
                                              const float* __restrict__ b1,
                                              const float* __restrict__ W2,
                                              const float* __restrict__ b2,
                                              float* __restrict__ out) {
    int warp = threadIdx.x >> 5, lane = threadIdx.x & 31;
    int i = blockIdx.x * 8 + warp;
    if (i >= NHYP) return;
    int idx = hyp[i];
    const float* hr = hfin + (size_t)idx * HID;
    float a0 = b1[lane], a1 = b1[lane + 32];
    for (int c = 0; c < HID; c++) {
        float hv = hr[c];
        a0 += hv * W1[c * 64 + lane];
        a1 += hv * W1[c * 64 + lane + 32];
    }
    a0 = fmaxf(a0, 0.0f);
    a1 = fmaxf(a1, 0.0f);
    float p = a0 * W2[lane] + a1 * W2[lane + 32];
    #pragma unroll
    for (int off = 16; off; off >>= 1) p += __shfl_xor_sync(0xFFFFFFFF, p, off);
    if (lane == 0) out[i] = p + b2[0];
}

// ---------------- launch ----------------
extern "C" void kernel_launch(void* const* d_in, const int* in_sizes, int n_in,
                              void* d_out, int out_size) {
    const float* x        = (const float*)d_in[0];
    const int*   ei       = (const int*)  d_in[1];
    const int*   hyp      = (const int*)  d_in[2];
    const float* enc_W1   = (const float*)d_in[3];
    const float* enc_b1   = (const float*)d_in[4];
    const float* enc_W2   = (const float*)d_in[5];
    const float* enc_b2   = (const float*)d_in[6];
    const float* gat_W    = (const float*)d_in[7];
    const float* att_src  = (const float*)d_in[8];
    const float* att_dst  = (const float*)d_in[9];
    const float* gat_b    = (const float*)d_in[10];
    const float* ln_g     = (const float*)d_in[11];
    const float* ln_b     = (const float*)d_in[12];
    const float* head_W1  = (const float*)d_in[13];
    const float* head_b1  = (const float*)d_in[14];
    const float* head_W2  = (const float*)d_in[15];
    const float* head_b2  = (const float*)d_in[16];
    float* out = (float*)d_out;

    float* d_hb = nullptr; cudaGetSymbolAddress((void**)&d_hb, g_hbuf);
    float* d_as = nullptr; cudaGetSymbolAddress((void**)&d_as, g_asb);
    float* d_ad = nullptr; cudaGetSymbolAddress((void**)&d_ad, g_adb);
    float* d_was = nullptr; cudaGetSymbolAddress((void**)&d_was, g_was);
    float* d_wad = nullptr; cudaGetSymbolAddress((void**)&d_wad, g_wad);
    __nv_bfloat16 *d_ah, *d_al, *d_wh, *d_wl, *d_weh, *d_wel;
    cudaGetSymbolAddress((void**)&d_ah,  g_a_hi);
    cudaGetSymbolAddress((void**)&d_al,  g_a_lo);
    cudaGetSymbolAddress((void**)&d_wh,  g_wt_hi);
    cudaGetSymbolAddress((void**)&d_wl,  g_wt_lo);
    cudaGetSymbolAddress((void**)&d_weh, g_wte_hi);
    cudaGetSymbolAddress((void**)&d_wel, g_wte_lo);

    float* hb[2] = { d_hb, d_hb + (size_t)NN * HID };
    float* asb[2] = { d_as, d_as + (size_t)NN * NH };
    float* adb[2] = { d_ad, d_ad + (size_t)NN * NH };

    static bool init_done = false;
    static cudaStream_t s2;
    static cudaEvent_t evFork, evJoin;
    if (!init_done) {
        cudaFuncSetAttribute(gemm2,   cudaFuncAttributeMaxDynamicSharedMemorySize, ENC_SMEM);
        cudaFuncSetAttribute(k_layer, cudaFuncAttributeMaxDynamicSharedMemorySize, LAY_SMEM);
        cudaStreamCreateWithFlags(&s2, cudaStreamNonBlocking);
        cudaEventCreateWithFlags(&evFork, cudaEventDisableTiming);
        cudaEventCreateWithFlags(&evJoin, cudaEventDisableTiming);
        init_done = true;
    }

    // ---- fork: CSR build + layer weight split on s2, encoder path on stream 0 ----
    cudaEventRecord(evFork, 0);
    cudaStreamWaitEvent(s2, evFork, 0);

    k_init_counts<<<(NN + 255) / 256, 256, 0, s2>>>();
    k_count<<<(EE + 255) / 256, 256, 0, s2>>>(ei + EE);
    k_scan1<<<SCAN_BLOCKS, 1024, 0, s2>>>();
    k_scan2<<<1, 64, 0, s2>>>();
    k_scan3<<<SCAN_BLOCKS, 1024, 0, s2>>>();
    k_scatter<<<(EP + 255) / 256, 256, 0, s2>>>(ei);
    k_wsplit_cat<<<(LL * HC * HID + 255) / 256, 256, 0, s2>>>(gat_W);

    k_wsplit<<<(HID * 128 + 255) / 256, 256>>>(enc_W2, d_weh, d_wel, HID);
    k_wattn<<<(LL * HC + 255) / 256, 256>>>(gat_W, att_src, att_dst);
    k_enc1<<<(NN * 32 + 255) / 256, 256>>>(x, enc_W1, enc_b1);
    gemm2<<<MT64, 256, ENC_SMEM>>>(d_ah, d_al, d_weh, d_wel,
                                   enc_b2, d_was, d_wad,
                                   hb[0], asb[0], adb[0], NN);

    cudaEventRecord(evJoin, s2);
    cudaStreamWaitEvent(0, evJoin, 0);

    // fused GAT layers (ping-pong buffers)
    for (int l = 0; l < LL; l++) {
        const float* nw_s = (l + 1 < LL) ? d_was + (l + 1) * HC : nullptr;
        const float* nw_d = (l + 1 < LL) ? d_wad + (l + 1) * HC : nullptr;
        k_layer<<<MT64, 256, LAY_SMEM>>>(
            d_wh + (size_t)l * HC * HID, d_wl + (size_t)l * HC * HID,
            gat_b + l * HID, ln_g + l * HID, ln_b + l * HID,
            nw_s, nw_d,
            hb[l & 1], hb[(l + 1) & 1],
            asb[l & 1], adb[l & 1],
            asb[(l + 1) & 1], adb[(l + 1) & 1]);
    }

    // head MLP on final buffer (LL=3 -> hb[1])
    k_head<<<(NHYP + 7) / 8, 256>>>(hyp, hb[1], head_W1, head_b1, head_W2, head_b2, out);
    (void)in_sizes; (void)n_in; (void)out_size;
}

// round 13
// speedup vs baseline: 1.6225x; 1.6225x over previous
#include <cuda_runtime.h>
#include <cuda_bf16.h>
#include <cuda_fp16.h>
#include <math_constants.h>
#include <cstdint>

// Problem constants
#define NN      50000
#define NPAD    50048       // MT64 * 64
#define EE      400000
#define EP      450000      // E + N self loops
#define D_IN    6
#define HID     128
#define NH      4
#define HC      512         // NH * 128
#define LL      3
#define NHYP    4096
#define MT64    782         // ceil(NN/64)
#define SCAN_BLOCKS 49

// ---------------- device scratch (static, no allocation) ----------------
__device__ float g_h  [NN * HID];            // current node features (fp32)
__device__ __nv_bfloat16 g_a_hi[NPAD * HID]; // encoder GEMM A operand (bf16 split)
__device__ __nv_bfloat16 g_a_lo[NPAD * HID];
__device__ __half g_z_hi[NPAD * HC];         // layer GEMM A operand (fp16 split)
__device__ __half g_z_lo[NPAD * HC];
__device__ float g_as [NN * NH];
__device__ float g_ad [NN * NH];
__device__ float g_was[LL * HC];
__device__ float g_wad[LL * HC];
__device__ int   g_cnt   [NN];
__device__ int   g_rowptr[NN + 1];
__device__ int   g_cursor[NN];
__device__ int   g_srcs  [EP];
__device__ int   g_bsum  [64];
__device__ __half g_wtf[LL * HC * HID];            // layer Wcat^T fp16: [l][c*512 + k]
__device__ __nv_bfloat16 g_wte_hi[HID * HID];      // encoder W2^T bf16 split [128,128]
__device__ __nv_bfloat16 g_wte_lo[HID * HID];

// ---------------- helpers ----------------
__device__ __forceinline__ uint32_t smem_u32(const void* p) {
    uint32_t a;
    asm("{ .reg .u64 t; cvta.to.shared.u64 t, %1; cvt.u32.u64 %0, t; }" : "=r"(a) : "l"(p));
    return a;
}
__device__ __forceinline__ void ldsm_x4(uint32_t& a0, uint32_t& a1, uint32_t& a2, uint32_t& a3, uint32_t addr) {
    asm volatile("ldmatrix.sync.aligned.m8n8.x4.shared.b16 {%0,%1,%2,%3}, [%4];"
                 : "=r"(a0), "=r"(a1), "=r"(a2), "=r"(a3) : "r"(addr));
}
__device__ __forceinline__ void mma_bf16(float* c, const uint32_t* a, uint32_t b0, uint32_t b1) {
    asm volatile("mma.sync.aligned.m16n8k16.row.col.f32.bf16.bf16.f32 "
                 "{%0,%1,%2,%3}, {%4,%5,%6,%7}, {%8,%9}, {%0,%1,%2,%3};"
                 : "+f"(c[0]), "+f"(c[1]), "+f"(c[2]), "+f"(c[3])
                 : "r"(a[0]), "r"(a[1]), "r"(a[2]), "r"(a[3]), "r"(b0), "r"(b1));
}
__device__ __forceinline__ void mma_f16(float* c, const uint32_t* a, uint32_t b0, uint32_t b1) {
    asm volatile("mma.sync.aligned.m16n8k16.row.col.f32.f16.f16.f32 "
                 "{%0,%1,%2,%3}, {%4,%5,%6,%7}, {%8,%9}, {%0,%1,%2,%3};"
                 : "+f"(c[0]), "+f"(c[1]), "+f"(c[2]), "+f"(c[3])
                 : "r"(a[0]), "r"(a[1]), "r"(a[2]), "r"(a[3]), "r"(b0), "r"(b1));
}
#define CP_ASYNC16(dst, src) asm volatile("cp.async.cg.shared.global [%0], [%1], 16;" :: "r"(dst), "l"(src))
#define CP_COMMIT()          asm volatile("cp.async.commit_group;" ::: "memory")
#define CP_WAIT0()           asm volatile("cp.async.wait_group 0;" ::: "memory")

__device__ __forceinline__ void split_bf16(float v, __nv_bfloat16& h, __nv_bfloat16& l) {
    h = __float2bfloat16(v);
    l = __float2bfloat16(v - __bfloat162float(h));
}
__device__ __forceinline__ void split_f16(float v, __half& h, __half& l) {
    h = __float2half(v);
    l = __float2half(v - __half2float(h));
}

// smem layout constants (row pitch 272B = 136 16-bit elems)
#define ROWB  272
#define ATILE (64 * ROWB)            // 17408
#define BTILE (128 * ROWB)           // 34816
// encoder gemm (K=128, bf16 3-term): A hi/lo + B hi/lo
#define OFF_AHI 0
#define OFF_ALO ATILE
#define OFF_BHI (2 * ATILE)
#define OFF_BLO (2 * ATILE + BTILE)
#define ENC_SMEM (2 * ATILE + 2 * BTILE)   // 104448 -> 2 CTAs/SM
// layer gemm (K=512, fp16 2-term): A hi/lo + B single
#define OFF_LB  (2 * ATILE)
#define LAY_SMEM (2 * ATILE + BTILE)       // 69632 -> 3 CTAs/SM
#define CS_STRIDE 133
// epilogue param offsets inside dynamic smem (after cs region, 34048B)
#define EP_WAS  34048
#define EP_WAD  36096
#define EP_BIAS 38144
#define EP_LNG  38656
#define EP_LNB  39168
#define EP_MU   39680
#define EP_RSTD 39936

// ================= encoder tensor-core GEMM (K=128, bf16 3-term) + dots epilogue =================
__global__ __launch_bounds__(256) void gemm_enc(
        const __nv_bfloat16* __restrict__ A_hi, const __nv_bfloat16* __restrict__ A_lo,
        const __nv_bfloat16* __restrict__ Bt_hi, const __nv_bfloat16* __restrict__ Bt_lo,
        const float* __restrict__ bias,
        const float* __restrict__ was, const float* __restrict__ wad,
        float* __restrict__ Cout,
        float* __restrict__ as_out, float* __restrict__ ad_out, int M) {
    extern __shared__ char smem[];
    __shared__ float s_was[HC], s_wad[HC];
    __shared__ float s_bias[128];
    const uint32_t sb = smem_u32(smem);
    const int tid = threadIdx.x, wid = tid >> 5, lane = tid & 31;
    const int rowBase = blockIdx.x * 64;

    if (tid < 128) s_bias[tid] = bias[tid];
    for (int i = tid; i < HC; i += 256) { s_was[i] = was[i]; s_wad[i] = wad[i]; }

    const int wm = wid & 1, wn = wid >> 1;
    const int mW = wm * 32, nW = wn * 32;
    float acc[2][4][4];
    #pragma unroll
    for (int mi = 0; mi < 2; mi++)
        #pragma unroll
        for (int ni = 0; ni < 4; ni++)
            #pragma unroll
            for (int j = 0; j < 4; j++) acc[mi][ni][j] = 0.f;

    const int aRow  = (lane & 15);
    const int aColB = ((lane >> 4) & 1) * 16;
    const int bRow  = ((lane >> 4) & 1) * 8 + (lane & 7);
    const int bColB = ((lane >> 3) & 1) * 16;
    const uint32_t aHi = sb + OFF_AHI, aLo = sb + OFF_ALO;
    const uint32_t bHi = sb + OFF_BHI, bLo = sb + OFF_BLO;

    #pragma unroll
    for (int i = 0; i < 8; i++) {
        int li = tid + 256 * i;
        int row = li >> 4, c8 = (li & 15) * 8;
        size_t gidx = (size_t)row * HID + c8;
        uint32_t off = (uint32_t)row * ROWB + (uint32_t)c8 * 2;
        CP_ASYNC16(sb + OFF_BHI + off, &Bt_hi[gidx]);
        CP_ASYNC16(sb + OFF_BLO + off, &Bt_lo[gidx]);
    }
    #pragma unroll
    for (int i = 0; i < 4; i++) {
        int li = tid + 256 * i;
        int row = li >> 4, c8 = (li & 15) * 8;
        size_t gidx = (size_t)(rowBase + row) * HID + c8;
        uint32_t off = (uint32_t)row * ROWB + (uint32_t)c8 * 2;
        CP_ASYNC16(sb + OFF_AHI + off, &A_hi[gidx]);
        CP_ASYNC16(sb + OFF_ALO + off, &A_lo[gidx]);
    }
    CP_COMMIT();
    CP_WAIT0();
    __syncthreads();

    #pragma unroll
    for (int kb = 0; kb < 8; kb++) {
        const uint32_t kByte = kb * 32;
        uint32_t ah[2][4], al[2][4], bh[4][2], bl[4][2];
        #pragma unroll
        for (int mi = 0; mi < 2; mi++) {
            uint32_t ao = (uint32_t)(mW + mi * 16 + aRow) * ROWB + kByte + aColB;
            ldsm_x4(ah[mi][0], ah[mi][1], ah[mi][2], ah[mi][3], aHi + ao);
            ldsm_x4(al[mi][0], al[mi][1], al[mi][2], al[mi][3], aLo + ao);
        }
        #pragma unroll
        for (int nj = 0; nj < 2; nj++) {
            uint32_t bo = (uint32_t)(nW + nj * 16 + bRow) * ROWB + kByte + bColB;
            ldsm_x4(bh[nj*2][0], bh[nj*2][1], bh[nj*2+1][0], bh[nj*2+1][1], bHi + bo);
            ldsm_x4(bl[nj*2][0], bl[nj*2][1], bl[nj*2+1][0], bl[nj*2+1][1], bLo + bo);
        }
        #pragma unroll
        for (int mi = 0; mi < 2; mi++)
            #pragma unroll
            for (int ni = 0; ni < 4; ni++) {
                mma_bf16(acc[mi][ni], ah[mi], bh[ni][0], bh[ni][1]);
                mma_bf16(acc[mi][ni], ah[mi], bl[ni][0], bl[ni][1]);
                mma_bf16(acc[mi][ni], al[mi], bh[ni][0], bh[ni][1]);
            }
    }
    __syncthreads();

    float* cs = (float*)smem;
    {
        const int r0 = (lane >> 2), c0 = (lane & 3) * 2;
        #pragma unroll
        for (int mi = 0; mi < 2; mi++)
            #pragma unroll
            for (int ni = 0; ni < 4; ni++) {
                int rr = mW + mi * 16 + r0;
                int cc = nW + ni * 8 + c0;
                cs[rr * CS_STRIDE + cc]           = acc[mi][ni][0];
                cs[rr * CS_STRIDE + cc + 1]       = acc[mi][ni][1];
                cs[(rr + 8) * CS_STRIDE + cc]     = acc[mi][ni][2];
                cs[(rr + 8) * CS_STRIDE + cc + 1] = acc[mi][ni][3];
            }
    }
    __syncthreads();

    #pragma unroll
    for (int i = 0; i < 8; i++) {
        int li = tid + 256 * i;
        int row = li >> 5, c4 = (li & 31) * 4;
        int gr = rowBase + row;
        float y0 = cs[row * CS_STRIDE + c4 + 0] + s_bias[c4 + 0];
        float y1 = cs[row * CS_STRIDE + c4 + 1] + s_bias[c4 + 1];
        float y2 = cs[row * CS_STRIDE + c4 + 2] + s_bias[c4 + 2];
        float y3 = cs[row * CS_STRIDE + c4 + 3] + s_bias[c4 + 3];
        cs[row * CS_STRIDE + c4 + 0] = y0;
        cs[row * CS_STRIDE + c4 + 1] = y1;
        cs[row * CS_STRIDE + c4 + 2] = y2;
        cs[row * CS_STRIDE + c4 + 3] = y3;
        if (gr < M)
            *(float4*)&Cout[(size_t)gr * HID + c4] = make_float4(y0, y1, y2, y3);
    }
    __syncthreads();

    if (tid < 128) {
        int row = tid >> 1, cb = (tid & 1) * 64;
        int gr = rowBase + row;
        float as[4] = {0, 0, 0, 0}, ad[4] = {0, 0, 0, 0};
        const float* cr = cs + row * CS_STRIDE;
        #pragma unroll 4
        for (int c = cb; c < cb + 64; c++) {
            float y = cr[c];
            #pragma unroll
            for (int h = 0; h < 4; h++) {
                as[h] += y * s_was[h * 128 + c];
                ad[h] += y * s_wad[h * 128 + c];
            }
        }
        #pragma unroll
        for (int h = 0; h < 4; h++) {
            as[h] += __shfl_down_sync(0xFFFFFFFF, as[h], 1);
            ad[h] += __shfl_down_sync(0xFFFFFFFF, ad[h], 1);
        }
        if (((tid & 1) == 0) && gr < M) {
            #pragma unroll
            for (int h = 0; h < 4; h++) {
                as_out[gr * 4 + h] = as[h];
                ad_out[gr * 4 + h] = ad[h];
            }
        }
    }
}

// ================= layer tensor-core GEMM (K=512, fp16 2-term) + fused epilogue =================
// C = relu(LN(0.25*(Z @ Wf^T) + bias)) + h (in-place residual); optional next-layer dots.
__global__ __launch_bounds__(256) void gemm_lay(
        const __half* __restrict__ Z_hi, const __half* __restrict__ Z_lo,
        const __half* __restrict__ Btf,
        const float* __restrict__ bias,
        const float* __restrict__ lng, const float* __restrict__ lnb,
        const float* __restrict__ was, const float* __restrict__ wad,
        float* __restrict__ Cout) {
    extern __shared__ char smem[];
    const uint32_t sb = smem_u32(smem);
    const int tid = threadIdx.x, wid = tid >> 5, lane = tid & 31;
    const int rowBase = blockIdx.x * 64;
    const bool dots = (was != nullptr);

    const int wm = wid & 1, wn = wid >> 1;
    const int mW = wm * 32, nW = wn * 32;
    float acc[2][4][4];
    #pragma unroll
    for (int mi = 0; mi < 2; mi++)
        #pragma unroll
        for (int ni = 0; ni < 4; ni++)
            #pragma unroll
            for (int j = 0; j < 4; j++) acc[mi][ni][j] = 0.f;

    const int aRow  = (lane & 15);
    const int aColB = ((lane >> 4) & 1) * 16;
    const int bRow  = ((lane >> 4) & 1) * 8 + (lane & 7);
    const int bColB = ((lane >> 3) & 1) * 16;
    const uint32_t aHi = sb + OFF_AHI, aLo = sb + OFF_ALO;
    const uint32_t bB  = sb + OFF_LB;

    for (int ch = 0; ch < 4; ch++) {
        const int kOff = ch * 128;
        #pragma unroll
        for (int i = 0; i < 8; i++) {
            int li = tid + 256 * i;
            int row = li >> 4, c8 = (li & 15) * 8;
            size_t gidx = (size_t)row * HC + kOff + c8;
            uint32_t off = (uint32_t)row * ROWB + (uint32_t)c8 * 2;
            CP_ASYNC16(bB + off, &Btf[gidx]);
        }
        #pragma unroll
        for (int i = 0; i < 4; i++) {
            int li = tid + 256 * i;
            int row = li >> 4, c8 = (li & 15) * 8;
            size_t gidx = (size_t)(rowBase + row) * HC + kOff + c8;
            uint32_t off = (uint32_t)row * ROWB + (uint32_t)c8 * 2;
            CP_ASYNC16(sb + OFF_AHI + off, &Z_hi[gidx]);
            CP_ASYNC16(sb + OFF_ALO + off, &Z_lo[gidx]);
        }
        CP_COMMIT();
        CP_WAIT0();
        __syncthreads();

        #pragma unroll
        for (int kb = 0; kb < 8; kb++) {
            const uint32_t kByte = kb * 32;
            uint32_t ah[2][4], al[2][4], bb[4][2];
            #pragma unroll
            for (int mi = 0; mi < 2; mi++) {
                uint32_t ao = (uint32_t)(mW + mi * 16 + aRow) * ROWB + kByte + aColB;
                ldsm_x4(ah[mi][0], ah[mi][1], ah[mi][2], ah[mi][3], aHi + ao);
                ldsm_x4(al[mi][0], al[mi][1], al[mi][2], al[mi][3], aLo + ao);
            }
            #pragma unroll
            for (int nj = 0; nj < 2; nj++) {
                uint32_t bo = (uint32_t)(nW + nj * 16 + bRow) * ROWB + kByte + bColB;
                ldsm_x4(bb[nj*2][0], bb[nj*2][1], bb[nj*2+1][0], bb[nj*2+1][1], bB + bo);
            }
            #pragma unroll
            for (int mi = 0; mi < 2; mi++)
                #pragma unroll
                for (int ni = 0; ni < 4; ni++) {
                    mma_f16(acc[mi][ni], ah[mi], bb[ni][0], bb[ni][1]);
                    mma_f16(acc[mi][ni], al[mi], bb[ni][0], bb[ni][1]);
                }
        }
        __syncthreads();
    }

    // --- epilogue: accum + params into dynamic smem ---
    float* cs     = (float*)smem;
    float* p_was  = (float*)(smem + EP_WAS);
    float* p_wad  = (float*)(smem + EP_WAD);
    float* p_bias = (float*)(smem + EP_BIAS);
    float* p_lng  = (float*)(smem + EP_LNG);
    float* p_lnb  = (float*)(smem + EP_LNB);
    float* p_mu   = (float*)(smem + EP_MU);
    float* p_rstd = (float*)(smem + EP_RSTD);

    {
        const int r0 = (lane >> 2), c0 = (lane & 3) * 2;
        #pragma unroll
        for (int mi = 0; mi < 2; mi++)
            #pragma unroll
            for (int ni = 0; ni < 4; ni++) {
                int rr = mW + mi * 16 + r0;
                int cc = nW + ni * 8 + c0;
                cs[rr * CS_STRIDE + cc]           = acc[mi][ni][0];
                cs[rr * CS_STRIDE + cc + 1]       = acc[mi][ni][1];
                cs[(rr + 8) * CS_STRIDE + cc]     = acc[mi][ni][2];
                cs[(rr + 8) * CS_STRIDE + cc + 1] = acc[mi][ni][3];
            }
    }
    if (tid < 128) { p_bias[tid] = bias[tid]; p_lng[tid] = lng[tid]; p_lnb[tid] = lnb[tid]; }
    if (dots)
        for (int i = tid; i < HC; i += 256) { p_was[i] = was[i]; p_wad[i] = wad[i]; }
    __syncthreads();

    #pragma unroll
    for (int i = 0; i < 8; i++) {
        int li = tid + 256 * i;
        int row = li >> 5, c4 = (li & 31) * 4;
        #pragma unroll
        for (int j = 0; j < 4; j++)
            cs[row * CS_STRIDE + c4 + j] = 0.25f * cs[row * CS_STRIDE + c4 + j] + p_bias[c4 + j];
    }
    __syncthreads();
    if (tid < 64) {
        const float* cr = cs + tid * CS_STRIDE;
        float sum = 0.f;
        #pragma unroll 8
        for (int c = 0; c < 128; c++) sum += cr[c];
        float mu = sum * (1.0f / 128.0f);
        float var = 0.f;
        #pragma unroll 8
        for (int c = 0; c < 128; c++) { float d = cr[c] - mu; var += d * d; }
        p_mu[tid] = mu;
        p_rstd[tid] = rsqrtf(var * (1.0f / 128.0f) + 1e-5f);
    }
    __syncthreads();
    #pragma unroll
    for (int i = 0; i < 8; i++) {
        int li = tid + 256 * i;
        int row = li >> 5, c4 = (li & 31) * 4;
        int gr = rowBase + row;
        float mu = p_mu[row], rs = p_rstd[row];
        float y[4];
        #pragma unroll
        for (int j = 0; j < 4; j++) {
            float v = (cs[row * CS_STRIDE + c4 + j] - mu) * rs * p_lng[c4 + j] + p_lnb[c4 + j];
            y[j] = fmaxf(v, 0.f);
        }
        if (gr < NN) {
            float4 res = *(const float4*)&Cout[(size_t)gr * HID + c4];
            float4 o = make_float4(y[0] + res.x, y[1] + res.y, y[2] + res.z, y[3] + res.w);
            *(float4*)&Cout[(size_t)gr * HID + c4] = o;
            cs[row * CS_STRIDE + c4 + 0] = o.x;
            cs[row * CS_STRIDE + c4 + 1] = o.y;
            cs[row * CS_STRIDE + c4 + 2] = o.z;
            cs[row * CS_STRIDE + c4 + 3] = o.w;
        }
    }
    __syncthreads();

    if (dots && tid < 128) {
        int row = tid >> 1, cb = (tid & 1) * 64;
        int gr = rowBase + row;
        float as[4] = {0, 0, 0, 0}, ad[4] = {0, 0, 0, 0};
        const float* cr = cs + row * CS_STRIDE;
        #pragma unroll 4
        for (int c = cb; c < cb + 64; c++) {
            float y = cr[c];
            #pragma unroll
            for (int h = 0; h < 4; h++) {
                as[h] += y * p_was[h * 128 + c];
                ad[h] += y * p_wad[h * 128 + c];
            }
        }
        #pragma unroll
        for (int h = 0; h < 4; h++) {
            as[h] += __shfl_down_sync(0xFFFFFFFF, as[h], 1);
            ad[h] += __shfl_down_sync(0xFFFFFFFF, ad[h], 1);
        }
        if (((tid & 1) == 0) && gr < NN) {
            #pragma unroll
            for (int h = 0; h < 4; h++) {
                g_as[gr * 4 + h] = as[h];
                g_ad[gr * 4 + h] = ad[h];
            }
        }
    }
}

// ---------------- encoder W2 transpose+split (bf16) ----------------
__global__ void k_wsplit(const float* __restrict__ W, __nv_bfloat16* __restrict__ hi,
                         __nv_bfloat16* __restrict__ lo, int NC) {
    int idx = blockIdx.x * blockDim.x + threadIdx.x;
    if (idx >= NC * 128) return;
    int n = idx >> 7, k = idx & 127;
    float x = W[k * NC + n];
    split_bf16(x, hi[idx], lo[idx]);
}

// ---------------- layer Wcat^T -> fp16 ----------------
__global__ void k_wsplit_cat(const float* __restrict__ gat_W) {
    int idx = blockIdx.x * blockDim.x + threadIdx.x;
    if (idx >= LL * HC * HID) return;
    int l = idx >> 16;
    int r = idx & 65535;
    int c = r >> 9;
    int k = r & 511;
    int j = k & 127, hh = k >> 7;
    float x = gat_W[(size_t)l * 65536 + j * 512 + hh * 128 + c];
    g_wtf[idx] = __float2half(x);
}

// ---------------- attn weight vectors ----------------
__global__ void k_wattn(const float* __restrict__ gat_W,
                        const float* __restrict__ att_src, const float* __restrict__ att_dst) {
    int idx = blockIdx.x * blockDim.x + threadIdx.x;
    if (idx >= LL * HC) return;
    int l = idx >> 9;
    int r = idx & 511;
    int hh = r >> 7, j = r & 127;
    const float* wr = gat_W + (size_t)l * 65536 + j * 512 + hh * 128;
    const float* as = att_src + l * HC + hh * 128;
    const float* ad = att_dst + l * HC + hh * 128;
    float sa = 0.f, sd = 0.f;
    #pragma unroll 8
    for (int c = 0; c < 128; c++) { sa += wr[c] * as[c]; sd += wr[c] * ad[c]; }
    g_was[idx] = sa;
    g_wad[idx] = sd;
}

// ---------------- CSR build ----------------
__global__ void k_init_counts() {
    int n = blockIdx.x * blockDim.x + threadIdx.x;
    if (n < NN) g_cnt[n] = 1;
}
__global__ void k_count(const int* __restrict__ dst) {
    int e = blockIdx.x * blockDim.x + threadIdx.x;
    if (e < EE) atomicAdd(&g_cnt[dst[e]], 1);
}
__global__ void k_scan1() {
    __shared__ int s[1024];
    int t = threadIdx.x;
    int i = blockIdx.x * 1024 + t;
    int v = (i < NN) ? g_cnt[i] : 0;
    s[t] = v;
    __syncthreads();
    #pragma unroll
    for (int off = 1; off < 1024; off <<= 1) {
        int x = (t >= off) ? s[t - off] : 0;
        __syncthreads();
        s[t] += x;
        __syncthreads();
    }
    if (i < NN) g_rowptr[i + 1] = s[t];
    if (t == 1023) g_bsum[blockIdx.x] = s[1023];
}
__global__ void k_scan2() {
    __shared__ int s[64];
    int t = threadIdx.x;
    int v = (t < SCAN_BLOCKS) ? g_bsum[t] : 0;
    s[t] = v;
    __syncthreads();
    #pragma unroll
    for (int off = 1; off < 64; off <<= 1) {
        int x = (t >= off) ? s[t - off] : 0;
        __syncthreads();
        s[t] += x;
        __syncthreads();
    }
    if (t < SCAN_BLOCKS) g_bsum[t] = s[t] - v;   // exclusive
}
__global__ void k_scan3() {
    int t = threadIdx.x;
    int i = blockIdx.x * 1024 + t;
    if (i < NN) {
        int v = g_rowptr[i + 1] + g_bsum[blockIdx.x];
        g_rowptr[i + 1] = v;
        if (i + 1 < NN) g_cursor[i + 1] = v;
    }
    if (i == 0) { g_rowptr[0] = 0; g_cursor[0] = 0; }
}
__global__ void k_scatter(const int* __restrict__ ei) {
    int e = blockIdx.x * blockDim.x + threadIdx.x;
    if (e >= EP) return;
    int s, d;
    if (e < EE) { s = ei[e]; d = ei[EE + e]; }
    else        { s = e - EE; d = s; }
    int pos = atomicAdd(&g_cursor[d], 1);
    g_srcs[pos] = s;
}

// ---------------- encoder first layer (K=6), W1 in smem, writes bf16 split ----------------
__global__ __launch_bounds__(256) void k_enc1(const float* __restrict__ x,
                                              const float* __restrict__ W1,
                                              const float* __restrict__ b1) {
    __shared__ float sW[D_IN * HID], sB[HID];
    int tid = threadIdx.x;
    for (int i = tid; i < D_IN * HID; i += 256) sW[i] = W1[i];
    if (tid < HID) sB[tid] = b1[tid];
    __syncthreads();

    int gid = blockIdx.x * 256 + tid;
    if (gid >= NN * 32) return;
    int n = gid >> 5, c4 = (gid & 31) * 4;
    const float* xr = x + n * D_IN;
    float xv[D_IN];
    #pragma unroll
    for (int k = 0; k < D_IN; k++) xv[k] = xr[k];
    __nv_bfloat16 hi[4], lo[4];
    #pragma unroll
    for (int j = 0; j < 4; j++) {
        int c = c4 + j;
        float acc = sB[c];
        #pragma unroll
        for (int k = 0; k < D_IN; k++) acc += xv[k] * sW[k * HID + c];
        split_bf16(fmaxf(acc, 0.0f), hi[j], lo[j]);
    }
    *(uint2*)&g_a_hi[(size_t)n * HID + c4] = *(uint2*)hi;
    *(uint2*)&g_a_lo[(size_t)n * HID + c4] = *(uint2*)lo;
}

// ---------------- h-space aggregation -> fp16 split z (K=512 layout) ----------------
__global__ __launch_bounds__(256) void k_aggh() {
    int warp = threadIdx.x >> 5, lane = threadIdx.x & 31;
    int n = blockIdx.x * 8 + warp;
    if (n >= NN) return;
    int r0 = g_rowptr[n], r1 = g_rowptr[n + 1];

    float4 adv = *(const float4*)&g_ad[n * 4];
    float adh[4] = {adv.x, adv.y, adv.z, adv.w};

    float m[4] = {-CUDART_INF_F, -CUDART_INF_F, -CUDART_INF_F, -CUDART_INF_F};
    for (int idx = r0 + lane; idx < r1; idx += 32) {
        int s = g_srcs[idx];
        float4 asv = *(const float4*)&g_as[s * 4];
        float e0 = asv.x + adh[0]; e0 = e0 > 0 ? e0 : 0.2f * e0; m[0] = fmaxf(m[0], e0);
        float e1 = asv.y + adh[1]; e1 = e1 > 0 ? e1 : 0.2f * e1; m[1] = fmaxf(m[1], e1);
        float e2 = asv.z + adh[2]; e2 = e2 > 0 ? e2 : 0.2f * e2; m[2] = fmaxf(m[2], e2);
        float e3 = asv.w + adh[3]; e3 = e3 > 0 ? e3 : 0.2f * e3; m[3] = fmaxf(m[3], e3);
    }
    #pragma unroll
    for (int off = 16; off; off >>= 1)
        #pragma unroll
        for (int h = 0; h < 4; h++)
            m[h] = fmaxf(m[h], __shfl_xor_sync(0xFFFFFFFF, m[h], off));

    float denom[4] = {0, 0, 0, 0};
    float z[4][4];
    #pragma unroll
    for (int h = 0; h < 4; h++)
        #pragma unroll
        for (int i = 0; i < 4; i++) z[h][i] = 0.f;

    for (int idx = r0; idx < r1; idx++) {
        int s = g_srcs[idx];
        float4 asv = *(const float4*)&g_as[s * 4];
        float ex[4];
        {
            float e;
            e = asv.x + adh[0]; e = e > 0 ? e : 0.2f * e; ex[0] = __expf(e - m[0]);
            e = asv.y + adh[1]; e = e > 0 ? e : 0.2f * e; ex[1] = __expf(e - m[1]);
            e = asv.z + adh[2]; e = e > 0 ? e : 0.2f * e; ex[2] = __expf(e - m[2]);
            e = asv.w + adh[3]; e = e > 0 ? e : 0.2f * e; ex[3] = __expf(e - m[3]);
        }
        denom[0] += ex[0]; denom[1] += ex[1]; denom[2] += ex[2]; denom[3] += ex[3];
        float4 hv = *(const float4*)&g_h[(size_t)s * HID + lane * 4];
        #pragma unroll
        for (int h = 0; h < 4; h++) {
            z[h][0] += ex[h] * hv.x;
            z[h][1] += ex[h] * hv.y;
            z[h][2] += ex[h] * hv.z;
            z[h][3] += ex[h] * hv.w;
        }
    }

    #pragma unroll
    for (int h = 0; h < 4; h++) {
        float inv = 1.0f / (denom[h] + 1e-16f);
        __half hi[4], lo[4];
        #pragma unroll
        for (int i = 0; i < 4; i++) split_f16(z[h][i] * inv, hi[i], lo[i]);
        size_t o = (size_t)n * HC + h * 128 + lane * 4;
        *(uint2*)&g_z_hi[o] = *(uint2*)hi;
        *(uint2*)&g_z_lo[o] = *(uint2*)lo;
    }
}

// ---------------- head MLP ----------------
__global__ __launch_bounds__(256) void k_head(const int* __restrict__ hyp,
                                              const float* __restrict__ W1,
                                              const float* __restrict__ b1,
                                              const float* __restrict__ W2,
                                              const float* __restrict__ b2,
                                              float* __restrict__ out) {
    int warp = threadIdx.x >> 5, lane = threadIdx.x & 31;
    int i = blockIdx.x * 8 + warp;
    if (i >= NHYP) return;
    int idx = hyp[i];
    const float* hr = g_h + (size_t)idx * HID;
    float a0 = b1[lane], a1 = b1[lane + 32];
    for (int c = 0; c < HID; c++) {
        float hv = hr[c];
        a0 += hv * W1[c * 64 + lane];
        a1 += hv * W1[c * 64 + lane + 32];
    }
    a0 = fmaxf(a0, 0.0f);
    a1 = fmaxf(a1, 0.0f);
    float p = a0 * W2[lane] + a1 * W2[lane + 32];
    #pragma unroll
    for (int off = 16; off; off >>= 1) p += __shfl_xor_sync(0xFFFFFFFF, p, off);
    if (lane == 0) out[i] = p + b2[0];
}

// ---------------- launch ----------------
extern "C" void kernel_launch(void* const* d_in, const int* in_sizes, int n_in,
                              void* d_out, int out_size) {
    const float* x        = (const float*)d_in[0];
    const int*   ei       = (const int*)  d_in[1];
    const int*   hyp      = (const int*)  d_in[2];
    const float* enc_W1   = (const float*)d_in[3];
    const float* enc_b1   = (const float*)d_in[4];
    const float* enc_W2   = (const float*)d_in[5];
    const float* enc_b2   = (const float*)d_in[6];
    const float* gat_W    = (const float*)d_in[7];
    const float* att_src  = (const float*)d_in[8];
    const float* att_dst  = (const float*)d_in[9];
    const float* gat_b    = (const float*)d_in[10];
    const float* ln_g     = (const float*)d_in[11];
    const float* ln_b     = (const float*)d_in[12];
    const float* head_W1  = (const float*)d_in[13];
    const float* head_b1  = (const float*)d_in[14];
    const float* head_W2  = (const float*)d_in[15];
    const float* head_b2  = (const float*)d_in[16];
    float* out = (float*)d_out;

    float* d_h  = nullptr; cudaGetSymbolAddress((void**)&d_h,  g_h);
    float* d_was = nullptr; cudaGetSymbolAddress((void**)&d_was, g_was);
    float* d_wad = nullptr; cudaGetSymbolAddress((void**)&d_wad, g_wad);
    float* d_as = nullptr; cudaGetSymbolAddress((void**)&d_as, g_as);
    float* d_ad = nullptr; cudaGetSymbolAddress((void**)&d_ad, g_ad);
    __nv_bfloat16 *d_ah, *d_al, *d_weh, *d_wel;
    __half *d_zh, *d_zl, *d_wtf;
    cudaGetSymbolAddress((void**)&d_ah,  g_a_hi);
    cudaGetSymbolAddress((void**)&d_al,  g_a_lo);
    cudaGetSymbolAddress((void**)&d_zh,  g_z_hi);
    cudaGetSymbolAddress((void**)&d_zl,  g_z_lo);
    cudaGetSymbolAddress((void**)&d_wtf, g_wtf);
    cudaGetSymbolAddress((void**)&d_weh, g_wte_hi);
    cudaGetSymbolAddress((void**)&d_wel, g_wte_lo);

    static bool init_done = false;
    static cudaStream_t s2;
    static cudaEvent_t evFork, evJoin;
    if (!init_done) {
        cudaFuncSetAttribute(gemm_enc, cudaFuncAttributeMaxDynamicSharedMemorySize, ENC_SMEM);
        cudaFuncSetAttribute(gemm_lay, cudaFuncAttributeMaxDynamicSharedMemorySize, LAY_SMEM);
        cudaStreamCreateWithFlags(&s2, cudaStreamNonBlocking);
        cudaEventCreateWithFlags(&evFork, cudaEventDisableTiming);
        cudaEventCreateWithFlags(&evJoin, cudaEventDisableTiming);
        init_done = true;
    }

    // ---- fork: CSR build + layer weight prep on s2, encoder path on stream 0 ----
    cudaEventRecord(evFork, 0);
    cudaStreamWaitEvent(s2, evFork, 0);

    k_init_counts<<<(NN + 255) / 256, 256, 0, s2>>>();
    k_count<<<(EE + 255) / 256, 256, 0, s2>>>(ei + EE);
    k_scan1<<<SCAN_BLOCKS, 1024, 0, s2>>>();
    k_scan2<<<1, 64, 0, s2>>>();
    k_scan3<<<SCAN_BLOCKS, 1024, 0, s2>>>();
    k_scatter<<<(EP + 255) / 256, 256, 0, s2>>>(ei);
    k_wsplit_cat<<<(LL * HC * HID + 255) / 256, 256, 0, s2>>>(gat_W);

    k_wsplit<<<(HID * 128 + 255) / 256, 256>>>(enc_W2, d_weh, d_wel, HID);
    k_wattn<<<(LL * HC + 255) / 256, 256>>>(gat_W, att_src, att_dst);
    k_enc1<<<(NN * 32 + 255) / 256, 256>>>(x, enc_W1, enc_b1);
    gemm_enc<<<MT64, 256, ENC_SMEM>>>(d_ah, d_al, d_weh, d_wel,
                                      enc_b2, d_was, d_wad,
                                      d_h, d_as, d_ad, NN);

    cudaEventRecord(evJoin, s2);
    cudaStreamWaitEvent(0, evJoin, 0);

    // GAT layers
    for (int l = 0; l < LL; l++) {
        k_aggh<<<(NN + 7) / 8, 256>>>();
        const float* nw_s = (l + 1 < LL) ? d_was + (l + 1) * HC : nullptr;
        const float* nw_d = (l + 1 < LL) ? d_wad + (l + 1) * HC : nullptr;
        gemm_lay<<<MT64, 256, LAY_SMEM>>>(d_zh, d_zl,
                                          d_wtf + (size_t)l * HC * HID,
                                          gat_b + l * HID, ln_g + l * HID, ln_b + l * HID,
                                          nw_s, nw_d, d_h);
    }

    // head MLP
    k_head<<<(NHYP + 7) / 8, 256>>>(hyp, head_W1, head_b1, head_W2, head_b2, out);
    (void)in_sizes; (void)n_in; (void)out_size;
}

// round 14
// speedup vs baseline: 1.8627x; 1.1480x over previous
#include <cuda_runtime.h>
#include <cuda_bf16.h>
#include <cuda_fp16.h>
#include <math_constants.h>
#include <cstdint>

// Problem constants
#define NN      50000
#define NPAD    50048       // MT64 * 64
#define EE      400000
#define EP      450000      // E + N self loops
#define D_IN    6
#define HID     128
#define NH      4
#define HC      512         // NH * 128
#define LL      3
#define NHYP    4096
#define MT64    782         // ceil(NN/64)
#define SCAN_BLOCKS 49

// ---------------- device scratch (static, no allocation) ----------------
__device__ float g_h  [NN * HID];            // current node features (fp32)
__device__ __nv_bfloat16 g_a_hi[NPAD * HID]; // encoder GEMM A operand (bf16 split)
__device__ __nv_bfloat16 g_a_lo[NPAD * HID];
__device__ __half g_z[NPAD * HC];            // layer GEMM A operand (fp16, single)
__device__ float g_as [NN * NH];
__device__ float g_ad [NN * NH];
__device__ float g_was[LL * HC];
__device__ float g_wad[LL * HC];
__device__ int   g_cnt   [NN];
__device__ int   g_rowptr[NN + 1];
__device__ int   g_cursor[NN];
__device__ int   g_srcs  [EP];
__device__ int   g_bsum  [64];
__device__ __half g_wtf[LL * HC * HID];            // layer Wcat^T fp16: [l][c*512 + k]
__device__ __nv_bfloat16 g_wte_hi[HID * HID];      // encoder W2^T bf16 split [128,128]
__device__ __nv_bfloat16 g_wte_lo[HID * HID];

// ---------------- helpers ----------------
__device__ __forceinline__ uint32_t smem_u32(const void* p) {
    uint32_t a;
    asm("{ .reg .u64 t; cvta.to.shared.u64 t, %1; cvt.u32.u64 %0, t; }" : "=r"(a) : "l"(p));
    return a;
}
__device__ __forceinline__ void ldsm_x4(uint32_t& a0, uint32_t& a1, uint32_t& a2, uint32_t& a3, uint32_t addr) {
    asm volatile("ldmatrix.sync.aligned.m8n8.x4.shared.b16 {%0,%1,%2,%3}, [%4];"
                 : "=r"(a0), "=r"(a1), "=r"(a2), "=r"(a3) : "r"(addr));
}
__device__ __forceinline__ void mma_bf16(float* c, const uint32_t* a, uint32_t b0, uint32_t b1) {
    asm volatile("mma.sync.aligned.m16n8k16.row.col.f32.bf16.bf16.f32 "
                 "{%0,%1,%2,%3}, {%4,%5,%6,%7}, {%8,%9}, {%0,%1,%2,%3};"
                 : "+f"(c[0]), "+f"(c[1]), "+f"(c[2]), "+f"(c[3])
                 : "r"(a[0]), "r"(a[1]), "r"(a[2]), "r"(a[3]), "r"(b0), "r"(b1));
}
__device__ __forceinline__ void mma_f16(float* c, const uint32_t* a, uint32_t b0, uint32_t b1) {
    asm volatile("mma.sync.aligned.m16n8k16.row.col.f32.f16.f16.f32 "
                 "{%0,%1,%2,%3}, {%4,%5,%6,%7}, {%8,%9}, {%0,%1,%2,%3};"
                 : "+f"(c[0]), "+f"(c[1]), "+f"(c[2]), "+f"(c[3])
                 : "r"(a[0]), "r"(a[1]), "r"(a[2]), "r"(a[3]), "r"(b0), "r"(b1));
}
#define CP_ASYNC16(dst, src) asm volatile("cp.async.cg.shared.global [%0], [%1], 16;" :: "r"(dst), "l"(src))
#define CP_COMMIT()          asm volatile("cp.async.commit_group;" ::: "memory")
#define CP_WAIT0()           asm volatile("cp.async.wait_group 0;" ::: "memory")

__device__ __forceinline__ void split_bf16(float v, __nv_bfloat16& h, __nv_bfloat16& l) {
    h = __float2bfloat16(v);
    l = __float2bfloat16(v - __bfloat162float(h));
}

// smem layout constants (row pitch 272B = 136 16-bit elems)
#define ROWB  272
#define ATILE (64 * ROWB)            // 17408
#define BTILE (128 * ROWB)           // 34816
// encoder gemm (K=128, bf16 3-term): A hi/lo + B hi/lo
#define OFF_AHI 0
#define OFF_ALO ATILE
#define OFF_BHI (2 * ATILE)
#define OFF_BLO (2 * ATILE + BTILE)
#define ENC_SMEM (2 * ATILE + 2 * BTILE)   // 104448 -> 2 CTAs/SM
// layer gemm (K=512, fp16 1-term): A single + B single
#define OFF_LA  0
#define OFF_LB  ATILE
#define LAY_SMEM (ATILE + BTILE)           // 52224 -> 4 CTAs/SM
#define CS_STRIDE 133
// epilogue param offsets inside dynamic smem (cs region = 34048B)
#define EP_WAS  34048
#define EP_WAD  36096
#define EP_BIAS 38144
#define EP_LNG  38656
#define EP_LNB  39168
#define EP_MU   39680
#define EP_RSTD 39936

// ================= encoder tensor-core GEMM (K=128, bf16 3-term) + dots epilogue =================
__global__ __launch_bounds__(256) void gemm_enc(
        const __nv_bfloat16* __restrict__ A_hi, const __nv_bfloat16* __restrict__ A_lo,
        const __nv_bfloat16* __restrict__ Bt_hi, const __nv_bfloat16* __restrict__ Bt_lo,
        const float* __restrict__ bias,
        const float* __restrict__ was, const float* __restrict__ wad,
        float* __restrict__ Cout,
        float* __restrict__ as_out, float* __restrict__ ad_out, int M) {
    extern __shared__ char smem[];
    __shared__ float s_was[HC], s_wad[HC];
    __shared__ float s_bias[128];
    const uint32_t sb = smem_u32(smem);
    const int tid = threadIdx.x, wid = tid >> 5, lane = tid & 31;
    const int rowBase = blockIdx.x * 64;

    if (tid < 128) s_bias[tid] = bias[tid];
    for (int i = tid; i < HC; i += 256) { s_was[i] = was[i]; s_wad[i] = wad[i]; }

    const int wm = wid & 1, wn = wid >> 1;
    const int mW = wm * 32, nW = wn * 32;
    float acc[2][4][4];
    #pragma unroll
    for (int mi = 0; mi < 2; mi++)
        #pragma unroll
        for (int ni = 0; ni < 4; ni++)
            #pragma unroll
            for (int j = 0; j < 4; j++) acc[mi][ni][j] = 0.f;

    const int aRow  = (lane & 15);
    const int aColB = ((lane >> 4) & 1) * 16;
    const int bRow  = ((lane >> 4) & 1) * 8 + (lane & 7);
    const int bColB = ((lane >> 3) & 1) * 16;
    const uint32_t aHi = sb + OFF_AHI, aLo = sb + OFF_ALO;
    const uint32_t bHi = sb + OFF_BHI, bLo = sb + OFF_BLO;

    #pragma unroll
    for (int i = 0; i < 8; i++) {
        int li = tid + 256 * i;
        int row = li >> 4, c8 = (li & 15) * 8;
        size_t gidx = (size_t)row * HID + c8;
        uint32_t off = (uint32_t)row * ROWB + (uint32_t)c8 * 2;
        CP_ASYNC16(sb + OFF_BHI + off, &Bt_hi[gidx]);
        CP_ASYNC16(sb + OFF_BLO + off, &Bt_lo[gidx]);
    }
    #pragma unroll
    for (int i = 0; i < 4; i++) {
        int li = tid + 256 * i;
        int row = li >> 4, c8 = (li & 15) * 8;
        size_t gidx = (size_t)(rowBase + row) * HID + c8;
        uint32_t off = (uint32_t)row * ROWB + (uint32_t)c8 * 2;
        CP_ASYNC16(sb + OFF_AHI + off, &A_hi[gidx]);
        CP_ASYNC16(sb + OFF_ALO + off, &A_lo[gidx]);
    }
    CP_COMMIT();
    CP_WAIT0();
    __syncthreads();

    #pragma unroll
    for (int kb = 0; kb < 8; kb++) {
        const uint32_t kByte = kb * 32;
        uint32_t ah[2][4], al[2][4], bh[4][2], bl[4][2];
        #pragma unroll
        for (int mi = 0; mi < 2; mi++) {
            uint32_t ao = (uint32_t)(mW + mi * 16 + aRow) * ROWB + kByte + aColB;
            ldsm_x4(ah[mi][0], ah[mi][1], ah[mi][2], ah[mi][3], aHi + ao);
            ldsm_x4(al[mi][0], al[mi][1], al[mi][2], al[mi][3], aLo + ao);
        }
        #pragma unroll
        for (int nj = 0; nj < 2; nj++) {
            uint32_t bo = (uint32_t)(nW + nj * 16 + bRow) * ROWB + kByte + bColB;
            ldsm_x4(bh[nj*2][0], bh[nj*2][1], bh[nj*2+1][0], bh[nj*2+1][1], bHi + bo);
            ldsm_x4(bl[nj*2][0], bl[nj*2][1], bl[nj*2+1][0], bl[nj*2+1][1], bLo + bo);
        }
        #pragma unroll
        for (int mi = 0; mi < 2; mi++)
            #pragma unroll
            for (int ni = 0; ni < 4; ni++) {
                mma_bf16(acc[mi][ni], ah[mi], bh[ni][0], bh[ni][1]);
                mma_bf16(acc[mi][ni], ah[mi], bl[ni][0], bl[ni][1]);
                mma_bf16(acc[mi][ni], al[mi], bh[ni][0], bh[ni][1]);
            }
    }
    __syncthreads();

    float* cs = (float*)smem;
    {
        const int r0 = (lane >> 2), c0 = (lane & 3) * 2;
        #pragma unroll
        for (int mi = 0; mi < 2; mi++)
            #pragma unroll
            for (int ni = 0; ni < 4; ni++) {
                int rr = mW + mi * 16 + r0;
                int cc = nW + ni * 8 + c0;
                cs[rr * CS_STRIDE + cc]           = acc[mi][ni][0];
                cs[rr * CS_STRIDE + cc + 1]       = acc[mi][ni][1];
                cs[(rr + 8) * CS_STRIDE + cc]     = acc[mi][ni][2];
                cs[(rr + 8) * CS_STRIDE + cc + 1] = acc[mi][ni][3];
            }
    }
    __syncthreads();

    #pragma unroll
    for (int i = 0; i < 8; i++) {
        int li = tid + 256 * i;
        int row = li >> 5, c4 = (li & 31) * 4;
        int gr = rowBase + row;
        float y0 = cs[row * CS_STRIDE + c4 + 0] + s_bias[c4 + 0];
        float y1 = cs[row * CS_STRIDE + c4 + 1] + s_bias[c4 + 1];
        float y2 = cs[row * CS_STRIDE + c4 + 2] + s_bias[c4 + 2];
        float y3 = cs[row * CS_STRIDE + c4 + 3] + s_bias[c4 + 3];
        cs[row * CS_STRIDE + c4 + 0] = y0;
        cs[row * CS_STRIDE + c4 + 1] = y1;
        cs[row * CS_STRIDE + c4 + 2] = y2;
        cs[row * CS_STRIDE + c4 + 3] = y3;
        if (gr < M)
            *(float4*)&Cout[(size_t)gr * HID + c4] = make_float4(y0, y1, y2, y3);
    }
    __syncthreads();

    if (tid < 128) {
        int row = tid >> 1, cb = (tid & 1) * 64;
        int gr = rowBase + row;
        float as[4] = {0, 0, 0, 0}, ad[4] = {0, 0, 0, 0};
        const float* cr = cs + row * CS_STRIDE;
        #pragma unroll 4
        for (int c = cb; c < cb + 64; c++) {
            float y = cr[c];
            #pragma unroll
            for (int h = 0; h < 4; h++) {
                as[h] += y * s_was[h * 128 + c];
                ad[h] += y * s_wad[h * 128 + c];
            }
        }
        #pragma unroll
        for (int h = 0; h < 4; h++) {
            as[h] += __shfl_down_sync(0xFFFFFFFF, as[h], 1);
            ad[h] += __shfl_down_sync(0xFFFFFFFF, ad[h], 1);
        }
        if (((tid & 1) == 0) && gr < M) {
            #pragma unroll
            for (int h = 0; h < 4; h++) {
                as_out[gr * 4 + h] = as[h];
                ad_out[gr * 4 + h] = ad[h];
            }
        }
    }
}

// ================= layer tensor-core GEMM (K=512, fp16 1-term) + fused epilogue =================
// C = relu(LN(0.25*(Z @ Wf^T) + bias)) + h (in-place residual); optional next-layer dots.
__global__ __launch_bounds__(256) void gemm_lay(
        const __half* __restrict__ Z,
        const __half* __restrict__ Btf,
        const float* __restrict__ bias,
        const float* __restrict__ lng, const float* __restrict__ lnb,
        const float* __restrict__ was, const float* __restrict__ wad,
        float* __restrict__ Cout) {
    extern __shared__ char smem[];
    const uint32_t sb = smem_u32(smem);
    const int tid = threadIdx.x, wid = tid >> 5, lane = tid & 31;
    const int rowBase = blockIdx.x * 64;
    const bool dots = (was != nullptr);

    const int wm = wid & 1, wn = wid >> 1;
    const int mW = wm * 32, nW = wn * 32;
    float acc[2][4][4];
    #pragma unroll
    for (int mi = 0; mi < 2; mi++)
        #pragma unroll
        for (int ni = 0; ni < 4; ni++)
            #pragma unroll
            for (int j = 0; j < 4; j++) acc[mi][ni][j] = 0.f;

    const int aRow  = (lane & 15);
    const int aColB = ((lane >> 4) & 1) * 16;
    const int bRow  = ((lane >> 4) & 1) * 8 + (lane & 7);
    const int bColB = ((lane >> 3) & 1) * 16;
    const uint32_t aB = sb + OFF_LA;
    const uint32_t bB = sb + OFF_LB;

    for (int ch = 0; ch < 4; ch++) {
        const int kOff = ch * 128;
        #pragma unroll
        for (int i = 0; i < 8; i++) {
            int li = tid + 256 * i;
            int row = li >> 4, c8 = (li & 15) * 8;
            size_t gidx = (size_t)row * HC + kOff + c8;
            uint32_t off = (uint32_t)row * ROWB + (uint32_t)c8 * 2;
            CP_ASYNC16(bB + off, &Btf[gidx]);
        }
        #pragma unroll
        for (int i = 0; i < 4; i++) {
            int li = tid + 256 * i;
            int row = li >> 4, c8 = (li & 15) * 8;
            size_t gidx = (size_t)(rowBase + row) * HC + kOff + c8;
            uint32_t off = (uint32_t)row * ROWB + (uint32_t)c8 * 2;
            CP_ASYNC16(aB + off, &Z[gidx]);
        }
        CP_COMMIT();
        CP_WAIT0();
        __syncthreads();

        #pragma unroll
        for (int kb = 0; kb < 8; kb++) {
            const uint32_t kByte = kb * 32;
            uint32_t ah[2][4], bb[4][2];
            #pragma unroll
            for (int mi = 0; mi < 2; mi++) {
                uint32_t ao = (uint32_t)(mW + mi * 16 + aRow) * ROWB + kByte + aColB;
                ldsm_x4(ah[mi][0], ah[mi][1], ah[mi][2], ah[mi][3], aB + ao);
            }
            #pragma unroll
            for (int nj = 0; nj < 2; nj++) {
                uint32_t bo = (uint32_t)(nW + nj * 16 + bRow) * ROWB + kByte + bColB;
                ldsm_x4(bb[nj*2][0], bb[nj*2][1], bb[nj*2+1][0], bb[nj*2+1][1], bB + bo);
            }
            #pragma unroll
            for (int mi = 0; mi < 2; mi++)
                #pragma unroll
                for (int ni = 0; ni < 4; ni++)
                    mma_f16(acc[mi][ni], ah[mi], bb[ni][0], bb[ni][1]);
        }
        __syncthreads();
    }

    // --- epilogue ---
    float* cs     = (float*)smem;
    float* p_was  = (float*)(smem + EP_WAS);
    float* p_wad  = (float*)(smem + EP_WAD);
    float* p_bias = (float*)(smem + EP_BIAS);
    float* p_lng  = (float*)(smem + EP_LNG);
    float* p_lnb  = (float*)(smem + EP_LNB);
    float* p_mu   = (float*)(smem + EP_MU);
    float* p_rstd = (float*)(smem + EP_RSTD);

    {
        const int r0 = (lane >> 2), c0 = (lane & 3) * 2;
        #pragma unroll
        for (int mi = 0; mi < 2; mi++)
            #pragma unroll
            for (int ni = 0; ni < 4; ni++) {
                int rr = mW + mi * 16 + r0;
                int cc = nW + ni * 8 + c0;
                cs[rr * CS_STRIDE + cc]           = acc[mi][ni][0];
                cs[rr * CS_STRIDE + cc + 1]       = acc[mi][ni][1];
                cs[(rr + 8) * CS_STRIDE + cc]     = acc[mi][ni][2];
                cs[(rr + 8) * CS_STRIDE + cc + 1] = acc[mi][ni][3];
            }
    }
    if (tid < 128) { p_bias[tid] = bias[tid]; p_lng[tid] = lng[tid]; p_lnb[tid] = lnb[tid]; }
    if (dots)
        for (int i = tid; i < HC; i += 256) { p_was[i] = was[i]; p_wad[i] = wad[i]; }
    __syncthreads();

    #pragma unroll
    for (int i = 0; i < 8; i++) {
        int li = tid + 256 * i;
        int row = li >> 5, c4 = (li & 31) * 4;
        #pragma unroll
        for (int j = 0; j < 4; j++)
            cs[row * CS_STRIDE + c4 + j] = 0.25f * cs[row * CS_STRIDE + c4 + j] + p_bias[c4 + j];
    }
    __syncthreads();
    if (tid < 64) {
        const float* cr = cs + tid * CS_STRIDE;
        float sum = 0.f;
        #pragma unroll 8
        for (int c = 0; c < 128; c++) sum += cr[c];
        float mu = sum * (1.0f / 128.0f);
        float var = 0.f;
        #pragma unroll 8
        for (int c = 0; c < 128; c++) { float d = cr[c] - mu; var += d * d; }
        p_mu[tid] = mu;
        p_rstd[tid] = rsqrtf(var * (1.0f / 128.0f) + 1e-5f);
    }
    __syncthreads();
    #pragma unroll
    for (int i = 0; i < 8; i++) {
        int li = tid + 256 * i;
        int row = li >> 5, c4 = (li & 31) * 4;
        int gr = rowBase + row;
        float mu = p_mu[row], rs = p_rstd[row];
        float y[4];
        #pragma unroll
        for (int j = 0; j < 4; j++) {
            float v = (cs[row * CS_STRIDE + c4 + j] - mu) * rs * p_lng[c4 + j] + p_lnb[c4 + j];
            y[j] = fmaxf(v, 0.f);
        }
        if (gr < NN) {
            float4 res = *(const float4*)&Cout[(size_t)gr * HID + c4];
            float4 o = make_float4(y[0] + res.x, y[1] + res.y, y[2] + res.z, y[3] + res.w);
            *(float4*)&Cout[(size_t)gr * HID + c4] = o;
            cs[row * CS_STRIDE + c4 + 0] = o.x;
            cs[row * CS_STRIDE + c4 + 1] = o.y;
            cs[row * CS_STRIDE + c4 + 2] = o.z;
            cs[row * CS_STRIDE + c4 + 3] = o.w;
        }
    }
    __syncthreads();

    if (dots && tid < 128) {
        int row = tid >> 1, cb = (tid & 1) * 64;
        int gr = rowBase + row;
        float as[4] = {0, 0, 0, 0}, ad[4] = {0, 0, 0, 0};
        const float* cr = cs + row * CS_STRIDE;
        #pragma unroll 4
        for (int c = cb; c < cb + 64; c++) {
            float y = cr[c];
            #pragma unroll
            for (int h = 0; h < 4; h++) {
                as[h] += y * p_was[h * 128 + c];
                ad[h] += y * p_wad[h * 128 + c];
            }
        }
        #pragma unroll
        for (int h = 0; h < 4; h++) {
            as[h] += __shfl_down_sync(0xFFFFFFFF, as[h], 1);
            ad[h] += __shfl_down_sync(0xFFFFFFFF, ad[h], 1);
        }
        if (((tid & 1) == 0) && gr < NN) {
            #pragma unroll
            for (int h = 0; h < 4; h++) {
                g_as[gr * 4 + h] = as[h];
                g_ad[gr * 4 + h] = ad[h];
            }
        }
    }
}

// ---------------- encoder W2 transpose+split (bf16) ----------------
__global__ void k_wsplit(const float* __restrict__ W, __nv_bfloat16* __restrict__ hi,
                         __nv_bfloat16* __restrict__ lo, int NC) {
    int idx = blockIdx.x * blockDim.x + threadIdx.x;
    if (idx >= NC * 128) return;
    int n = idx >> 7, k = idx & 127;
    float x = W[k * NC + n];
    split_bf16(x, hi[idx], lo[idx]);
}

// ---------------- layer Wcat^T -> fp16 ----------------
__global__ void k_wsplit_cat(const float* __restrict__ gat_W) {
    int idx = blockIdx.x * blockDim.x + threadIdx.x;
    if (idx >= LL * HC * HID) return;
    int l = idx >> 16;
    int r = idx & 65535;
    int c = r >> 9;
    int k = r & 511;
    int j = k & 127, hh = k >> 7;
    float x = gat_W[(size_t)l * 65536 + j * 512 + hh * 128 + c];
    g_wtf[idx] = __float2half(x);
}

// ---------------- attn weight vectors ----------------
__global__ void k_wattn(const float* __restrict__ gat_W,
                        const float* __restrict__ att_src, const float* __restrict__ att_dst) {
    int idx = blockIdx.x * blockDim.x + threadIdx.x;
    if (idx >= LL * HC) return;
    int l = idx >> 9;
    int r = idx & 511;
    int hh = r >> 7, j = r & 127;
    const float* wr = gat_W + (size_t)l * 65536 + j * 512 + hh * 128;
    const float* as = att_src + l * HC + hh * 128;
    const float* ad = att_dst + l * HC + hh * 128;
    float sa = 0.f, sd = 0.f;
    #pragma unroll 8
    for (int c = 0; c < 128; c++) { sa += wr[c] * as[c]; sd += wr[c] * ad[c]; }
    g_was[idx] = sa;
    g_wad[idx] = sd;
}

// ---------------- CSR build ----------------
__global__ void k_init_counts() {
    int n = blockIdx.x * blockDim.x + threadIdx.x;
    if (n < NN) g_cnt[n] = 1;
}
__global__ void k_count(const int* __restrict__ dst) {
    int e = blockIdx.x * blockDim.x + threadIdx.x;
    if (e < EE) atomicAdd(&g_cnt[dst[e]], 1);
}
__global__ void k_scan1() {
    __shared__ int s[1024];
    int t = threadIdx.x;
    int i = blockIdx.x * 1024 + t;
    int v = (i < NN) ? g_cnt[i] : 0;
    s[t] = v;
    __syncthreads();
    #pragma unroll
    for (int off = 1; off < 1024; off <<= 1) {
        int x = (t >= off) ? s[t - off] : 0;
        __syncthreads();
        s[t] += x;
        __syncthreads();
    }
    if (i < NN) g_rowptr[i + 1] = s[t];
    if (t == 1023) g_bsum[blockIdx.x] = s[1023];
}
__global__ void k_scan2() {
    __shared__ int s[64];
    int t = threadIdx.x;
    int v = (t < SCAN_BLOCKS) ? g_bsum[t] : 0;
    s[t] = v;
    __syncthreads();
    #pragma unroll
    for (int off = 1; off < 64; off <<= 1) {
        int x = (t >= off) ? s[t - off] : 0;
        __syncthreads();
        s[t] += x;
        __syncthreads();
    }
    if (t < SCAN_BLOCKS) g_bsum[t] = s[t] - v;   // exclusive
}
__global__ void k_scan3() {
    int t = threadIdx.x;
    int i = blockIdx.x * 1024 + t;
    if (i < NN) {
        int v = g_rowptr[i + 1] + g_bsum[blockIdx.x];
        g_rowptr[i + 1] = v;
        if (i + 1 < NN) g_cursor[i + 1] = v;
    }
    if (i == 0) { g_rowptr[0] = 0; g_cursor[0] = 0; }
}
__global__ void k_scatter(const int* __restrict__ ei) {
    int e = blockIdx.x * blockDim.x + threadIdx.x;
    if (e >= EP) return;
    int s, d;
    if (e < EE) { s = ei[e]; d = ei[EE + e]; }
    else        { s = e - EE; d = s; }
    int pos = atomicAdd(&g_cursor[d], 1);
    g_srcs[pos] = s;
}

// ---------------- encoder first layer (K=6), W1 in smem, writes bf16 split ----------------
__global__ __launch_bounds__(256) void k_enc1(const float* __restrict__ x,
                                              const float* __restrict__ W1,
                                              const float* __restrict__ b1) {
    __shared__ float sW[D_IN * HID], sB[HID];
    int tid = threadIdx.x;
    for (int i = tid; i < D_IN * HID; i += 256) sW[i] = W1[i];
    if (tid < HID) sB[tid] = b1[tid];
    __syncthreads();

    int gid = blockIdx.x * 256 + tid;
    if (gid >= NN * 32) return;
    int n = gid >> 5, c4 = (gid & 31) * 4;
    const float* xr = x + n * D_IN;
    float xv[D_IN];
    #pragma unroll
    for (int k = 0; k < D_IN; k++) xv[k] = xr[k];
    __nv_bfloat16 hi[4], lo[4];
    #pragma unroll
    for (int j = 0; j < 4; j++) {
        int c = c4 + j;
        float acc = sB[c];
        #pragma unroll
        for (int k = 0; k < D_IN; k++) acc += xv[k] * sW[k * HID + c];
        split_bf16(fmaxf(acc, 0.0f), hi[j], lo[j]);
    }
    *(uint2*)&g_a_hi[(size_t)n * HID + c4] = *(uint2*)hi;
    *(uint2*)&g_a_lo[(size_t)n * HID + c4] = *(uint2*)lo;
}

// ---------------- h-space aggregation -> fp16 z (K=512 layout) ----------------
__global__ __launch_bounds__(256) void k_aggh() {
    int warp = threadIdx.x >> 5, lane = threadIdx.x & 31;
    int n = blockIdx.x * 8 + warp;
    if (n >= NN) return;
    int r0 = g_rowptr[n], r1 = g_rowptr[n + 1];

    float4 adv = *(const float4*)&g_ad[n * 4];
    float adh[4] = {adv.x, adv.y, adv.z, adv.w};

    float m[4] = {-CUDART_INF_F, -CUDART_INF_F, -CUDART_INF_F, -CUDART_INF_F};
    for (int idx = r0 + lane; idx < r1; idx += 32) {
        int s = g_srcs[idx];
        float4 asv = *(const float4*)&g_as[s * 4];
        float e0 = asv.x + adh[0]; e0 = e0 > 0 ? e0 : 0.2f * e0; m[0] = fmaxf(m[0], e0);
        float e1 = asv.y + adh[1]; e1 = e1 > 0 ? e1 : 0.2f * e1; m[1] = fmaxf(m[1], e1);
        float e2 = asv.z + adh[2]; e2 = e2 > 0 ? e2 : 0.2f * e2; m[2] = fmaxf(m[2], e2);
        float e3 = asv.w + adh[3]; e3 = e3 > 0 ? e3 : 0.2f * e3; m[3] = fmaxf(m[3], e3);
    }
    #pragma unroll
    for (int off = 16; off; off >>= 1)
        #pragma unroll
        for (int h = 0; h < 4; h++)
            m[h] = fmaxf(m[h], __shfl_xor_sync(0xFFFFFFFF, m[h], off));

    float denom[4] = {0, 0, 0, 0};
    float z[4][4];
    #pragma unroll
    for (int h = 0; h < 4; h++)
        #pragma unroll
        for (int i = 0; i < 4; i++) z[h][i] = 0.f;

    for (int idx = r0; idx < r1; idx++) {
        int s = g_srcs[idx];
        float4 asv = *(const float4*)&g_as[s * 4];
        float ex[4];
        {
            float e;
            e = asv.x + adh[0]; e = e > 0 ? e : 0.2f * e; ex[0] = __expf(e - m[0]);
            e = asv.y + adh[1]; e = e > 0 ? e : 0.2f * e; ex[1] = __expf(e - m[1]);
            e = asv.z + adh[2]; e = e > 0 ? e : 0.2f * e; ex[2] = __expf(e - m[2]);
            e = asv.w + adh[3]; e = e > 0 ? e : 0.2f * e; ex[3] = __expf(e - m[3]);
        }
        denom[0] += ex[0]; denom[1] += ex[1]; denom[2] += ex[2]; denom[3] += ex[3];
        float4 hv = *(const float4*)&g_h[(size_t)s * HID + lane * 4];
        #pragma unroll
        for (int h = 0; h < 4; h++) {
            z[h][0] += ex[h] * hv.x;
            z[h][1] += ex[h] * hv.y;
            z[h][2] += ex[h] * hv.z;
            z[h][3] += ex[h] * hv.w;
        }
    }

    #pragma unroll
    for (int h = 0; h < 4; h++) {
        float inv = 1.0f / (denom[h] + 1e-16f);
        __half zz[4];
        #pragma unroll
        for (int i = 0; i < 4; i++) zz[i] = __float2half(z[h][i] * inv);
        size_t o = (size_t)n * HC + h * 128 + lane * 4;
        *(uint2*)&g_z[o] = *(uint2*)zz;
    }
}

// ---------------- head MLP ----------------
__global__ __launch_bounds__(256) void k_head(const int* __restrict__ hyp,
                                              const float* __restrict__ W1,
                                              const float* __restrict__ b1,
                                              const float* __restrict__ W2,
                                              const float* __restrict__ b2,
                                              float* __restrict__ out) {
    int warp = threadIdx.x >> 5, lane = threadIdx.x & 31;
    int i = blockIdx.x * 8 + warp;
    if (i >= NHYP) return;
    int idx = hyp[i];
    const float* hr = g_h + (size_t)idx * HID;
    float a0 = b1[lane], a1 = b1[lane + 32];
    for (int c = 0; c < HID; c++) {
        float hv = hr[c];
        a0 += hv * W1[c * 64 + lane];
        a1 += hv * W1[c * 64 + lane + 32];
    }
    a0 = fmaxf(a0, 0.0f);
    a1 = fmaxf(a1, 0.0f);
    float p = a0 * W2[lane] + a1 * W2[lane + 32];
    #pragma unroll
    for (int off = 16; off; off >>= 1) p += __shfl_xor_sync(0xFFFFFFFF, p, off);
    if (lane == 0) out[i] = p + b2[0];
}

// ---------------- launch ----------------
extern "C" void kernel_launch(void* const* d_in, const int* in_sizes, int n_in,
                              void* d_out, int out_size) {
    const float* x        = (const float*)d_in[0];
    const int*   ei       = (const int*)  d_in[1];
    const int*   hyp      = (const int*)  d_in[2];
    const float* enc_W1   = (const float*)d_in[3];
    const float* enc_b1   = (const float*)d_in[4];
    const float* enc_W2   = (const float*)d_in[5];
    const float* enc_b2   = (const float*)d_in[6];
    const float* gat_W    = (const float*)d_in[7];
    const float* att_src  = (const float*)d_in[8];
    const float* att_dst  = (const float*)d_in[9];
    const float* gat_b    = (const float*)d_in[10];
    const float* ln_g     = (const float*)d_in[11];
    const float* ln_b     = (const float*)d_in[12];
    const float* head_W1  = (const float*)d_in[13];
    const float* head_b1  = (const float*)d_in[14];
    const float* head_W2  = (const float*)d_in[15];
    const float* head_b2  = (const float*)d_in[16];
    float* out = (float*)d_out;

    float* d_h  = nullptr; cudaGetSymbolAddress((void**)&d_h,  g_h);
    float* d_was = nullptr; cudaGetSymbolAddress((void**)&d_was, g_was);
    float* d_wad = nullptr; cudaGetSymbolAddress((void**)&d_wad, g_wad);
    float* d_as = nullptr; cudaGetSymbolAddress((void**)&d_as, g_as);
    float* d_ad = nullptr; cudaGetSymbolAddress((void**)&d_ad, g_ad);
    __nv_bfloat16 *d_ah, *d_al, *d_weh, *d_wel;
    __half *d_z, *d_wtf;
    cudaGetSymbolAddress((void**)&d_ah,  g_a_hi);
    cudaGetSymbolAddress((void**)&d_al,  g_a_lo);
    cudaGetSymbolAddress((void**)&d_z,   g_z);
    cudaGetSymbolAddress((void**)&d_wtf, g_wtf);
    cudaGetSymbolAddress((void**)&d_weh, g_wte_hi);
    cudaGetSymbolAddress((void**)&d_wel, g_wte_lo);

    static bool init_done = false;
    static cudaStream_t s2;
    static cudaEvent_t evFork, evJoin;
    if (!init_done) {
        cudaFuncSetAttribute(gemm_enc, cudaFuncAttributeMaxDynamicSharedMemorySize, ENC_SMEM);
        cudaFuncSetAttribute(gemm_lay, cudaFuncAttributeMaxDynamicSharedMemorySize, LAY_SMEM);
        cudaStreamCreateWithFlags(&s2, cudaStreamNonBlocking);
        cudaEventCreateWithFlags(&evFork, cudaEventDisableTiming);
        cudaEventCreateWithFlags(&evJoin, cudaEventDisableTiming);
        init_done = true;
    }

    // ---- fork: CSR build + layer weight prep on s2, encoder path on stream 0 ----
    cudaEventRecord(evFork, 0);
    cudaStreamWaitEvent(s2, evFork, 0);

    k_init_counts<<<(NN + 255) / 256, 256, 0, s2>>>();
    k_count<<<(EE + 255) / 256, 256, 0, s2>>>(ei + EE);
    k_scan1<<<SCAN_BLOCKS, 1024, 0, s2>>>();
    k_scan2<<<1, 64, 0, s2>>>();
    k_scan3<<<SCAN_BLOCKS, 1024, 0, s2>>>();
    k_scatter<<<(EP + 255) / 256, 256, 0, s2>>>(ei);
    k_wsplit_cat<<<(LL * HC * HID + 255) / 256, 256, 0, s2>>>(gat_W);

    k_wsplit<<<(HID * 128 + 255) / 256, 256>>>(enc_W2, d_weh, d_wel, HID);
    k_wattn<<<(LL * HC + 255) / 256, 256>>>(gat_W, att_src, att_dst);
    k_enc1<<<(NN * 32 + 255) / 256, 256>>>(x, enc_W1, enc_b1);
    gemm_enc<<<MT64, 256, ENC_SMEM>>>(d_ah, d_al, d_weh, d_wel,
                                      enc_b2, d_was, d_wad,
                                      d_h, d_as, d_ad, NN);

    cudaEventRecord(evJoin, s2);
    cudaStreamWaitEvent(0, evJoin, 0);

    // GAT layers
    for (int l = 0; l < LL; l++) {
        k_aggh<<<(NN + 7) / 8, 256>>>();
        const float* nw_s = (l + 1 < LL) ? d_was + (l + 1) * HC : nullptr;
        const float* nw_d = (l + 1 < LL) ? d_wad + (l + 1) * HC : nullptr;
        gemm_lay<<<MT64, 256, LAY_SMEM>>>(d_z,
                                          d_wtf + (size_t)l * HC * HID,
                                          gat_b + l * HID, ln_g + l * HID, ln_b + l * HID,
                                          nw_s, nw_d, d_h);
    }

    // head MLP
    k_head<<<(NHYP + 7) / 8, 256>>>(hyp, head_W1, head_b1, head_W2, head_b2, out);
    (void)in_sizes; (void)n_in; (void)out_size;
}

// round 15
// speedup vs baseline: 1.9169x; 1.0291x over previous
#include <cuda_runtime.h>
#include <cuda_bf16.h>
#include <cuda_fp16.h>
#include <math_constants.h>
#include <cstdint>

// Problem constants
#define NN      50000
#define NPAD    50048       // MT64 * 64
#define EE      400000
#define EP      450000      // E + N self loops
#define D_IN    6
#define HID     128
#define NH      4
#define HC      512         // NH * 128
#define LL      3
#define NHYP    4096
#define MT64    782         // ceil(NN/64)
#define SCAN_BLOCKS 49

// ---------------- device scratch (static, no allocation) ----------------
__device__ float g_h  [NN * HID];            // current node features (fp32, residual/head path)
__device__ __half g_hf[NN * HID];            // fp16 shadow of h (gather path)
__device__ __nv_bfloat16 g_a_hi[NPAD * HID]; // encoder GEMM A operand (bf16 split)
__device__ __nv_bfloat16 g_a_lo[NPAD * HID];
__device__ __half g_z[NPAD * HC];            // layer GEMM A operand (fp16)
__device__ float g_as [NN * NH];
__device__ float g_ad [NN * NH];
__device__ float g_was[LL * HC];
__device__ float g_wad[LL * HC];
__device__ int   g_cnt   [NN];
__device__ int   g_rowptr[NN + 1];
__device__ int   g_cursor[NN];
__device__ int   g_srcs  [EP];
__device__ int   g_bsum  [64];
__device__ __half g_wtf[LL * HC * HID];            // layer Wcat^T fp16: [l][c*512 + k]
__device__ __nv_bfloat16 g_wte_hi[HID * HID];      // encoder W2^T bf16 split [128,128]
__device__ __nv_bfloat16 g_wte_lo[HID * HID];

// ---------------- helpers ----------------
__device__ __forceinline__ uint32_t smem_u32(const void* p) {
    uint32_t a;
    asm("{ .reg .u64 t; cvta.to.shared.u64 t, %1; cvt.u32.u64 %0, t; }" : "=r"(a) : "l"(p));
    return a;
}
__device__ __forceinline__ void ldsm_x4(uint32_t& a0, uint32_t& a1, uint32_t& a2, uint32_t& a3, uint32_t addr) {
    asm volatile("ldmatrix.sync.aligned.m8n8.x4.shared.b16 {%0,%1,%2,%3}, [%4];"
                 : "=r"(a0), "=r"(a1), "=r"(a2), "=r"(a3) : "r"(addr));
}
__device__ __forceinline__ void mma_bf16(float* c, const uint32_t* a, uint32_t b0, uint32_t b1) {
    asm volatile("mma.sync.aligned.m16n8k16.row.col.f32.bf16.bf16.f32 "
                 "{%0,%1,%2,%3}, {%4,%5,%6,%7}, {%8,%9}, {%0,%1,%2,%3};"
                 : "+f"(c[0]), "+f"(c[1]), "+f"(c[2]), "+f"(c[3])
                 : "r"(a[0]), "r"(a[1]), "r"(a[2]), "r"(a[3]), "r"(b0), "r"(b1));
}
__device__ __forceinline__ void mma_f16(float* c, const uint32_t* a, uint32_t b0, uint32_t b1) {
    asm volatile("mma.sync.aligned.m16n8k16.row.col.f32.f16.f16.f32 "
                 "{%0,%1,%2,%3}, {%4,%5,%6,%7}, {%8,%9}, {%0,%1,%2,%3};"
                 : "+f"(c[0]), "+f"(c[1]), "+f"(c[2]), "+f"(c[3])
                 : "r"(a[0]), "r"(a[1]), "r"(a[2]), "r"(a[3]), "r"(b0), "r"(b1));
}
#define CP_ASYNC16(dst, src) asm volatile("cp.async.cg.shared.global [%0], [%1], 16;" :: "r"(dst), "l"(src))
#define CP_COMMIT()          asm volatile("cp.async.commit_group;" ::: "memory")
#define CP_WAIT0()           asm volatile("cp.async.wait_group 0;" ::: "memory")

__device__ __forceinline__ void split_bf16(float v, __nv_bfloat16& h, __nv_bfloat16& l) {
    h = __float2bfloat16(v);
    l = __float2bfloat16(v - __bfloat162float(h));
}

// smem layout constants (row pitch 272B = 136 16-bit elems)
#define ROWB  272
#define ATILE (64 * ROWB)            // 17408
#define BTILE (128 * ROWB)           // 34816
// encoder gemm (K=128, bf16 3-term): A hi/lo + B hi/lo
#define OFF_AHI 0
#define OFF_ALO ATILE
#define OFF_BHI (2 * ATILE)
#define OFF_BLO (2 * ATILE + BTILE)
#define ENC_SMEM (2 * ATILE + 2 * BTILE)   // 104448 -> 2 CTAs/SM
// layer gemm (K=512, fp16 1-term): A single + B single
#define OFF_LA  0
#define OFF_LB  ATILE
#define LAY_SMEM (ATILE + BTILE)           // 52224 -> 4 CTAs/SM
#define CS_STRIDE 133
// epilogue param offsets inside dynamic smem (cs region = 34048B)
#define EP_WAS  34048
#define EP_WAD  36096
#define EP_BIAS 38144
#define EP_LNG  38656
#define EP_LNB  39168
#define EP_MU   39680
#define EP_RSTD 39936

// ================= encoder tensor-core GEMM (K=128, bf16 3-term) + dots epilogue =================
__global__ __launch_bounds__(256) void gemm_enc(
        const __nv_bfloat16* __restrict__ A_hi, const __nv_bfloat16* __restrict__ A_lo,
        const __nv_bfloat16* __restrict__ Bt_hi, const __nv_bfloat16* __restrict__ Bt_lo,
        const float* __restrict__ bias,
        const float* __restrict__ was, const float* __restrict__ wad,
        float* __restrict__ Cout,
        float* __restrict__ as_out, float* __restrict__ ad_out, int M) {
    extern __shared__ char smem[];
    __shared__ float s_was[HC], s_wad[HC];
    __shared__ float s_bias[128];
    const uint32_t sb = smem_u32(smem);
    const int tid = threadIdx.x, wid = tid >> 5, lane = tid & 31;
    const int rowBase = blockIdx.x * 64;

    if (tid < 128) s_bias[tid] = bias[tid];
    for (int i = tid; i < HC; i += 256) { s_was[i] = was[i]; s_wad[i] = wad[i]; }

    const int wm = wid & 1, wn = wid >> 1;
    const int mW = wm * 32, nW = wn * 32;
    float acc[2][4][4];
    #pragma unroll
    for (int mi = 0; mi < 2; mi++)
        #pragma unroll
        for (int ni = 0; ni < 4; ni++)
            #pragma unroll
            for (int j = 0; j < 4; j++) acc[mi][ni][j] = 0.f;

    const int aRow  = (lane & 15);
    const int aColB = ((lane >> 4) & 1) * 16;
    const int bRow  = ((lane >> 4) & 1) * 8 + (lane & 7);
    const int bColB = ((lane >> 3) & 1) * 16;
    const uint32_t aHi = sb + OFF_AHI, aLo = sb + OFF_ALO;
    const uint32_t bHi = sb + OFF_BHI, bLo = sb + OFF_BLO;

    #pragma unroll
    for (int i = 0; i < 8; i++) {
        int li = tid + 256 * i;
        int row = li >> 4, c8 = (li & 15) * 8;
        size_t gidx = (size_t)row * HID + c8;
        uint32_t off = (uint32_t)row * ROWB + (uint32_t)c8 * 2;
        CP_ASYNC16(sb + OFF_BHI + off, &Bt_hi[gidx]);
        CP_ASYNC16(sb + OFF_BLO + off, &Bt_lo[gidx]);
    }
    #pragma unroll
    for (int i = 0; i < 4; i++) {
        int li = tid + 256 * i;
        int row = li >> 4, c8 = (li & 15) * 8;
        size_t gidx = (size_t)(rowBase + row) * HID + c8;
        uint32_t off = (uint32_t)row * ROWB + (uint32_t)c8 * 2;
        CP_ASYNC16(sb + OFF_AHI + off, &A_hi[gidx]);
        CP_ASYNC16(sb + OFF_ALO + off, &A_lo[gidx]);
    }
    CP_COMMIT();
    CP_WAIT0();
    __syncthreads();

    #pragma unroll
    for (int kb = 0; kb < 8; kb++) {
        const uint32_t kByte = kb * 32;
        uint32_t ah[2][4], al[2][4], bh[4][2], bl[4][2];
        #pragma unroll
        for (int mi = 0; mi < 2; mi++) {
            uint32_t ao = (uint32_t)(mW + mi * 16 + aRow) * ROWB + kByte + aColB;
            ldsm_x4(ah[mi][0], ah[mi][1], ah[mi][2], ah[mi][3], aHi + ao);
            ldsm_x4(al[mi][0], al[mi][1], al[mi][2], al[mi][3], aLo + ao);
        }
        #pragma unroll
        for (int nj = 0; nj < 2; nj++) {
            uint32_t bo = (uint32_t)(nW + nj * 16 + bRow) * ROWB + kByte + bColB;
            ldsm_x4(bh[nj*2][0], bh[nj*2][1], bh[nj*2+1][0], bh[nj*2+1][1], bHi + bo);
            ldsm_x4(bl[nj*2][0], bl[nj*2][1], bl[nj*2+1][0], bl[nj*2+1][1], bLo + bo);
        }
        #pragma unroll
        for (int mi = 0; mi < 2; mi++)
            #pragma unroll
            for (int ni = 0; ni < 4; ni++) {
                mma_bf16(acc[mi][ni], ah[mi], bh[ni][0], bh[ni][1]);
                mma_bf16(acc[mi][ni], ah[mi], bl[ni][0], bl[ni][1]);
                mma_bf16(acc[mi][ni], al[mi], bh[ni][0], bh[ni][1]);
            }
    }
    __syncthreads();

    float* cs = (float*)smem;
    {
        const int r0 = (lane >> 2), c0 = (lane & 3) * 2;
        #pragma unroll
        for (int mi = 0; mi < 2; mi++)
            #pragma unroll
            for (int ni = 0; ni < 4; ni++) {
                int rr = mW + mi * 16 + r0;
                int cc = nW + ni * 8 + c0;
                cs[rr * CS_STRIDE + cc]           = acc[mi][ni][0];
                cs[rr * CS_STRIDE + cc + 1]       = acc[mi][ni][1];
                cs[(rr + 8) * CS_STRIDE + cc]     = acc[mi][ni][2];
                cs[(rr + 8) * CS_STRIDE + cc + 1] = acc[mi][ni][3];
            }
    }
    __syncthreads();

    #pragma unroll
    for (int i = 0; i < 8; i++) {
        int li = tid + 256 * i;
        int row = li >> 5, c4 = (li & 31) * 4;
        int gr = rowBase + row;
        float y0 = cs[row * CS_STRIDE + c4 + 0] + s_bias[c4 + 0];
        float y1 = cs[row * CS_STRIDE + c4 + 1] + s_bias[c4 + 1];
        float y2 = cs[row * CS_STRIDE + c4 + 2] + s_bias[c4 + 2];
        float y3 = cs[row * CS_STRIDE + c4 + 3] + s_bias[c4 + 3];
        cs[row * CS_STRIDE + c4 + 0] = y0;
        cs[row * CS_STRIDE + c4 + 1] = y1;
        cs[row * CS_STRIDE + c4 + 2] = y2;
        cs[row * CS_STRIDE + c4 + 3] = y3;
        if (gr < M) {
            *(float4*)&Cout[(size_t)gr * HID + c4] = make_float4(y0, y1, y2, y3);
            __half hf[4] = {__float2half(y0), __float2half(y1), __float2half(y2), __float2half(y3)};
            *(uint2*)&g_hf[(size_t)gr * HID + c4] = *(uint2*)hf;
        }
    }
    __syncthreads();

    if (tid < 128) {
        int row = tid >> 1, cb = (tid & 1) * 64;
        int gr = rowBase + row;
        float as[4] = {0, 0, 0, 0}, ad[4] = {0, 0, 0, 0};
        const float* cr = cs + row * CS_STRIDE;
        #pragma unroll 4
        for (int c = cb; c < cb + 64; c++) {
            float y = cr[c];
            #pragma unroll
            for (int h = 0; h < 4; h++) {
                as[h] += y * s_was[h * 128 + c];
                ad[h] += y * s_wad[h * 128 + c];
            }
        }
        #pragma unroll
        for (int h = 0; h < 4; h++) {
            as[h] += __shfl_down_sync(0xFFFFFFFF, as[h], 1);
            ad[h] += __shfl_down_sync(0xFFFFFFFF, ad[h], 1);
        }
        if (((tid & 1) == 0) && gr < M) {
            #pragma unroll
            for (int h = 0; h < 4; h++) {
                as_out[gr * 4 + h] = as[h];
                ad_out[gr * 4 + h] = ad[h];
            }
        }
    }
}

// ================= layer tensor-core GEMM (K=512, fp16 1-term) + fused epilogue =================
__global__ __launch_bounds__(256) void gemm_lay(
        const __half* __restrict__ Z,
        const __half* __restrict__ Btf,
        const float* __restrict__ bias,
        const float* __restrict__ lng, const float* __restrict__ lnb,
        const float* __restrict__ was, const float* __restrict__ wad,
        float* __restrict__ Cout) {
    extern __shared__ char smem[];
    const uint32_t sb = smem_u32(smem);
    const int tid = threadIdx.x, wid = tid >> 5, lane = tid & 31;
    const int rowBase = blockIdx.x * 64;
    const bool dots = (was != nullptr);

    const int wm = wid & 1, wn = wid >> 1;
    const int mW = wm * 32, nW = wn * 32;
    float acc[2][4][4];
    #pragma unroll
    for (int mi = 0; mi < 2; mi++)
        #pragma unroll
        for (int ni = 0; ni < 4; ni++)
            #pragma unroll
            for (int j = 0; j < 4; j++) acc[mi][ni][j] = 0.f;

    const int aRow  = (lane & 15);
    const int aColB = ((lane >> 4) & 1) * 16;
    const int bRow  = ((lane >> 4) & 1) * 8 + (lane & 7);
    const int bColB = ((lane >> 3) & 1) * 16;
    const uint32_t aB = sb + OFF_LA;
    const uint32_t bB = sb + OFF_LB;

    for (int ch = 0; ch < 4; ch++) {
        const int kOff = ch * 128;
        #pragma unroll
        for (int i = 0; i < 8; i++) {
            int li = tid + 256 * i;
            int row = li >> 4, c8 = (li & 15) * 8;
            size_t gidx = (size_t)row * HC + kOff + c8;
            uint32_t off = (uint32_t)row * ROWB + (uint32_t)c8 * 2;
            CP_ASYNC16(bB + off, &Btf[gidx]);
        }
        #pragma unroll
        for (int i = 0; i < 4; i++) {
            int li = tid + 256 * i;
            int row = li >> 4, c8 = (li & 15) * 8;
            size_t gidx = (size_t)(rowBase + row) * HC + kOff + c8;
            uint32_t off = (uint32_t)row * ROWB + (uint32_t)c8 * 2;
            CP_ASYNC16(aB + off, &Z[gidx]);
        }
        CP_COMMIT();
        CP_WAIT0();
        __syncthreads();

        #pragma unroll
        for (int kb = 0; kb < 8; kb++) {
            const uint32_t kByte = kb * 32;
            uint32_t ah[2][4], bb[4][2];
            #pragma unroll
            for (int mi = 0; mi < 2; mi++) {
                uint32_t ao = (uint32_t)(mW + mi * 16 + aRow) * ROWB + kByte + aColB;
                ldsm_x4(ah[mi][0], ah[mi][1], ah[mi][2], ah[mi][3], aB + ao);
            }
            #pragma unroll
            for (int nj = 0; nj < 2; nj++) {
                uint32_t bo = (uint32_t)(nW + nj * 16 + bRow) * ROWB + kByte + bColB;
                ldsm_x4(bb[nj*2][0], bb[nj*2][1], bb[nj*2+1][0], bb[nj*2+1][1], bB + bo);
            }
            #pragma unroll
            for (int mi = 0; mi < 2; mi++)
                #pragma unroll
                for (int ni = 0; ni < 4; ni++)
                    mma_f16(acc[mi][ni], ah[mi], bb[ni][0], bb[ni][1]);
        }
        __syncthreads();
    }

    // --- epilogue ---
    float* cs     = (float*)smem;
    float* p_was  = (float*)(smem + EP_WAS);
    float* p_wad  = (float*)(smem + EP_WAD);
    float* p_bias = (float*)(smem + EP_BIAS);
    float* p_lng  = (float*)(smem + EP_LNG);
    float* p_lnb  = (float*)(smem + EP_LNB);
    float* p_mu   = (float*)(smem + EP_MU);
    float* p_rstd = (float*)(smem + EP_RSTD);

    {
        const int r0 = (lane >> 2), c0 = (lane & 3) * 2;
        #pragma unroll
        for (int mi = 0; mi < 2; mi++)
            #pragma unroll
            for (int ni = 0; ni < 4; ni++) {
                int rr = mW + mi * 16 + r0;
                int cc = nW + ni * 8 + c0;
                cs[rr * CS_STRIDE + cc]           = acc[mi][ni][0];
                cs[rr * CS_STRIDE + cc + 1]       = acc[mi][ni][1];
                cs[(rr + 8) * CS_STRIDE + cc]     = acc[mi][ni][2];
                cs[(rr + 8) * CS_STRIDE + cc + 1] = acc[mi][ni][3];
            }
    }
    if (tid < 128) { p_bias[tid] = bias[tid]; p_lng[tid] = lng[tid]; p_lnb[tid] = lnb[tid]; }
    if (dots)
        for (int i = tid; i < HC; i += 256) { p_was[i] = was[i]; p_wad[i] = wad[i]; }
    __syncthreads();

    #pragma unroll
    for (int i = 0; i < 8; i++) {
        int li = tid + 256 * i;
        int row = li >> 5, c4 = (li & 31) * 4;
        #pragma unroll
        for (int j = 0; j < 4; j++)
            cs[row * CS_STRIDE + c4 + j] = 0.25f * cs[row * CS_STRIDE + c4 + j] + p_bias[c4 + j];
    }
    __syncthreads();
    if (tid < 64) {
        const float* cr = cs + tid * CS_STRIDE;
        float sum = 0.f;
        #pragma unroll 8
        for (int c = 0; c < 128; c++) sum += cr[c];
        float mu = sum * (1.0f / 128.0f);
        float var = 0.f;
        #pragma unroll 8
        for (int c = 0; c < 128; c++) { float d = cr[c] - mu; var += d * d; }
        p_mu[tid] = mu;
        p_rstd[tid] = rsqrtf(var * (1.0f / 128.0f) + 1e-5f);
    }
    __syncthreads();
    #pragma unroll
    for (int i = 0; i < 8; i++) {
        int li = tid + 256 * i;
        int row = li >> 5, c4 = (li & 31) * 4;
        int gr = rowBase + row;
        float mu = p_mu[row], rs = p_rstd[row];
        float y[4];
        #pragma unroll
        for (int j = 0; j < 4; j++) {
            float v = (cs[row * CS_STRIDE + c4 + j] - mu) * rs * p_lng[c4 + j] + p_lnb[c4 + j];
            y[j] = fmaxf(v, 0.f);
        }
        if (gr < NN) {
            float4 res = *(const float4*)&Cout[(size_t)gr * HID + c4];
            float4 o = make_float4(y[0] + res.x, y[1] + res.y, y[2] + res.z, y[3] + res.w);
            *(float4*)&Cout[(size_t)gr * HID + c4] = o;
            __half hf[4] = {__float2half(o.x), __float2half(o.y), __float2half(o.z), __float2half(o.w)};
            *(uint2*)&g_hf[(size_t)gr * HID + c4] = *(uint2*)hf;
            cs[row * CS_STRIDE + c4 + 0] = o.x;
            cs[row * CS_STRIDE + c4 + 1] = o.y;
            cs[row * CS_STRIDE + c4 + 2] = o.z;
            cs[row * CS_STRIDE + c4 + 3] = o.w;
        }
    }
    __syncthreads();

    if (dots && tid < 128) {
        int row = tid >> 1, cb = (tid & 1) * 64;
        int gr = rowBase + row;
        float as[4] = {0, 0, 0, 0}, ad[4] = {0, 0, 0, 0};
        const float* cr = cs + row * CS_STRIDE;
        #pragma unroll 4
        for (int c = cb; c < cb + 64; c++) {
            float y = cr[c];
            #pragma unroll
            for (int h = 0; h < 4; h++) {
                as[h] += y * p_was[h * 128 + c];
                ad[h] += y * p_wad[h * 128 + c];
            }
        }
        #pragma unroll
        for (int h = 0; h < 4; h++) {
            as[h] += __shfl_down_sync(0xFFFFFFFF, as[h], 1);
            ad[h] += __shfl_down_sync(0xFFFFFFFF, ad[h], 1);
        }
        if (((tid & 1) == 0) && gr < NN) {
            #pragma unroll
            for (int h = 0; h < 4; h++) {
                g_as[gr * 4 + h] = as[h];
                g_ad[gr * 4 + h] = ad[h];
            }
        }
    }
}

// ---------------- encoder W2 transpose+split (bf16) ----------------
__global__ void k_wsplit(const float* __restrict__ W, __nv_bfloat16* __restrict__ hi,
                         __nv_bfloat16* __restrict__ lo, int NC) {
    int idx = blockIdx.x * blockDim.x + threadIdx.x;
    if (idx >= NC * 128) return;
    int n = idx >> 7, k = idx & 127;
    float x = W[k * NC + n];
    split_bf16(x, hi[idx], lo[idx]);
}

// ---------------- layer Wcat^T -> fp16 ----------------
__global__ void k_wsplit_cat(const float* __restrict__ gat_W) {
    int idx = blockIdx.x * blockDim.x + threadIdx.x;
    if (idx >= LL * HC * HID) return;
    int l = idx >> 16;
    int r = idx & 65535;
    int c = r >> 9;
    int k = r & 511;
    int j = k & 127, hh = k >> 7;
    float x = gat_W[(size_t)l * 65536 + j * 512 + hh * 128 + c];
    g_wtf[idx] = __float2half(x);
}

// ---------------- attn weight vectors ----------------
__global__ void k_wattn(const float* __restrict__ gat_W,
                        const float* __restrict__ att_src, const float* __restrict__ att_dst) {
    int idx = blockIdx.x * blockDim.x + threadIdx.x;
    if (idx >= LL * HC) return;
    int l = idx >> 9;
    int r = idx & 511;
    int hh = r >> 7, j = r & 127;
    const float* wr = gat_W + (size_t)l * 65536 + j * 512 + hh * 128;
    const float* as = att_src + l * HC + hh * 128;
    const float* ad = att_dst + l * HC + hh * 128;
    float sa = 0.f, sd = 0.f;
    #pragma unroll 8
    for (int c = 0; c < 128; c++) { sa += wr[c] * as[c]; sd += wr[c] * ad[c]; }
    g_was[idx] = sa;
    g_wad[idx] = sd;
}

// ---------------- CSR build ----------------
__global__ void k_init_counts() {
    int n = blockIdx.x * blockDim.x + threadIdx.x;
    if (n < NN) g_cnt[n] = 1;
}
__global__ void k_count(const int* __restrict__ dst) {
    int e = blockIdx.x * blockDim.x + threadIdx.x;
    if (e < EE) atomicAdd(&g_cnt[dst[e]], 1);
}
__global__ void k_scan1() {
    __shared__ int s[1024];
    int t = threadIdx.x;
    int i = blockIdx.x * 1024 + t;
    int v = (i < NN) ? g_cnt[i] : 0;
    s[t] = v;
    __syncthreads();
    #pragma unroll
    for (int off = 1; off < 1024; off <<= 1) {
        int x = (t >= off) ? s[t - off] : 0;
        __syncthreads();
        s[t] += x;
        __syncthreads();
    }
    if (i < NN) g_rowptr[i + 1] = s[t];
    if (t == 1023) g_bsum[blockIdx.x] = s[1023];
}
__global__ void k_scan2() {
    __shared__ int s[64];
    int t = threadIdx.x;
    int v = (t < SCAN_BLOCKS) ? g_bsum[t] : 0;
    s[t] = v;
    __syncthreads();
    #pragma unroll
    for (int off = 1; off < 64; off <<= 1) {
        int x = (t >= off) ? s[t - off] : 0;
        __syncthreads();
        s[t] += x;
        __syncthreads();
    }
    if (t < SCAN_BLOCKS) g_bsum[t] = s[t] - v;   // exclusive
}
__global__ void k_scan3() {
    int t = threadIdx.x;
    int i = blockIdx.x * 1024 + t;
    if (i < NN) {
        int v = g_rowptr[i + 1] + g_bsum[blockIdx.x];
        g_rowptr[i + 1] = v;
        if (i + 1 < NN) g_cursor[i + 1] = v;
    }
    if (i == 0) { g_rowptr[0] = 0; g_cursor[0] = 0; }
}
__global__ void k_scatter(const int* __restrict__ ei) {
    int e = blockIdx.x * blockDim.x + threadIdx.x;
    if (e >= EP) return;
    int s, d;
    if (e < EE) { s = ei[e]; d = ei[EE + e]; }
    else        { s = e - EE; d = s; }
    int pos = atomicAdd(&g_cursor[d], 1);
    g_srcs[pos] = s;
}

// ---------------- encoder first layer (K=6), W1 in smem, writes bf16 split ----------------
__global__ __launch_bounds__(256) void k_enc1(const float* __restrict__ x,
                                              const float* __restrict__ W1,
                                              const float* __restrict__ b1) {
    __shared__ float sW[D_IN * HID], sB[HID];
    int tid = threadIdx.x;
    for (int i = tid; i < D_IN * HID; i += 256) sW[i] = W1[i];
    if (tid < HID) sB[tid] = b1[tid];
    __syncthreads();

    int gid = blockIdx.x * 256 + tid;
    if (gid >= NN * 32) return;
    int n = gid >> 5, c4 = (gid & 31) * 4;
    const float* xr = x + n * D_IN;
    float xv[D_IN];
    #pragma unroll
    for (int k = 0; k < D_IN; k++) xv[k] = xr[k];
    __nv_bfloat16 hi[4], lo[4];
    #pragma unroll
    for (int j = 0; j < 4; j++) {
        int c = c4 + j;
        float acc = sB[c];
        #pragma unroll
        for (int k = 0; k < D_IN; k++) acc += xv[k] * sW[k * HID + c];
        split_bf16(fmaxf(acc, 0.0f), hi[j], lo[j]);
    }
    *(uint2*)&g_a_hi[(size_t)n * HID + c4] = *(uint2*)hi;
    *(uint2*)&g_a_lo[(size_t)n * HID + c4] = *(uint2*)lo;
}

// ---------------- h-space aggregation (fp16 h gather) -> fp16 z ----------------
__global__ __launch_bounds__(256) void k_aggh() {
    int warp = threadIdx.x >> 5, lane = threadIdx.x & 31;
    int n = blockIdx.x * 8 + warp;
    if (n >= NN) return;
    int r0 = g_rowptr[n], r1 = g_rowptr[n + 1];

    float4 adv = *(const float4*)&g_ad[n * 4];
    float adh[4] = {adv.x, adv.y, adv.z, adv.w};

    float m[4] = {-CUDART_INF_F, -CUDART_INF_F, -CUDART_INF_F, -CUDART_INF_F};
    for (int idx = r0 + lane; idx < r1; idx += 32) {
        int s = g_srcs[idx];
        float4 asv = *(const float4*)&g_as[s * 4];
        float e0 = asv.x + adh[0]; e0 = e0 > 0 ? e0 : 0.2f * e0; m[0] = fmaxf(m[0], e0);
        float e1 = asv.y + adh[1]; e1 = e1 > 0 ? e1 : 0.2f * e1; m[1] = fmaxf(m[1], e1);
        float e2 = asv.z + adh[2]; e2 = e2 > 0 ? e2 : 0.2f * e2; m[2] = fmaxf(m[2], e2);
        float e3 = asv.w + adh[3]; e3 = e3 > 0 ? e3 : 0.2f * e3; m[3] = fmaxf(m[3], e3);
    }
    #pragma unroll
    for (int off = 16; off; off >>= 1)
        #pragma unroll
        for (int h = 0; h < 4; h++)
            m[h] = fmaxf(m[h], __shfl_xor_sync(0xFFFFFFFF, m[h], off));

    float denom[4] = {0, 0, 0, 0};
    float z[4][4];
    #pragma unroll
    for (int h = 0; h < 4; h++)
        #pragma unroll
        for (int i = 0; i < 4; i++) z[h][i] = 0.f;

    for (int idx = r0; idx < r1; idx++) {
        int s = g_srcs[idx];
        float4 asv = *(const float4*)&g_as[s * 4];
        float ex[4];
        {
            float e;
            e = asv.x + adh[0]; e = e > 0 ? e : 0.2f * e; ex[0] = __expf(e - m[0]);
            e = asv.y + adh[1]; e = e > 0 ? e : 0.2f * e; ex[1] = __expf(e - m[1]);
            e = asv.z + adh[2]; e = e > 0 ? e : 0.2f * e; ex[2] = __expf(e - m[2]);
            e = asv.w + adh[3]; e = e > 0 ? e : 0.2f * e; ex[3] = __expf(e - m[3]);
        }
        denom[0] += ex[0]; denom[1] += ex[1]; denom[2] += ex[2]; denom[3] += ex[3];
        uint2 hv2 = *(const uint2*)&g_hf[(size_t)s * HID + lane * 4];
        float2 f01 = __half22float2(*(__half2*)&hv2.x);
        float2 f23 = __half22float2(*(__half2*)&hv2.y);
        #pragma unroll
        for (int h = 0; h < 4; h++) {
            z[h][0] += ex[h] * f01.x;
            z[h][1] += ex[h] * f01.y;
            z[h][2] += ex[h] * f23.x;
            z[h][3] += ex[h] * f23.y;
        }
    }

    #pragma unroll
    for (int h = 0; h < 4; h++) {
        float inv = 1.0f / (denom[h] + 1e-16f);
        __half zz[4];
        #pragma unroll
        for (int i = 0; i < 4; i++) zz[i] = __float2half(z[h][i] * inv);
        size_t o = (size_t)n * HC + h * 128 + lane * 4;
        *(uint2*)&g_z[o] = *(uint2*)zz;
    }
}

// ---------------- head MLP ----------------
__global__ __launch_bounds__(256) void k_head(const int* __restrict__ hyp,
                                              const float* __restrict__ W1,
                                              const float* __restrict__ b1,
                                              const float* __restrict__ W2,
                                              const float* __restrict__ b2,
                                              float* __restrict__ out) {
    int warp = threadIdx.x >> 5, lane = threadIdx.x & 31;
    int i = blockIdx.x * 8 + warp;
    if (i >= NHYP) return;
    int idx = hyp[i];
    const float* hr = g_h + (size_t)idx * HID;
    float a0 = b1[lane], a1 = b1[lane + 32];
    for (int c = 0; c < HID; c++) {
        float hv = hr[c];
        a0 += hv * W1[c * 64 + lane];
        a1 += hv * W1[c * 64 + lane + 32];
    }
    a0 = fmaxf(a0, 0.0f);
    a1 = fmaxf(a1, 0.0f);
    float p = a0 * W2[lane] + a1 * W2[lane + 32];
    #pragma unroll
    for (int off = 16; off; off >>= 1) p += __shfl_xor_sync(0xFFFFFFFF, p, off);
    if (lane == 0) out[i] = p + b2[0];
}

// ---------------- launch ----------------
extern "C" void kernel_launch(void* const* d_in, const int* in_sizes, int n_in,
                              void* d_out, int out_size) {
    const float* x        = (const float*)d_in[0];
    const int*   ei       = (const int*)  d_in[1];
    const int*   hyp      = (const int*)  d_in[2];
    const float* enc_W1   = (const float*)d_in[3];
    const float* enc_b1   = (const float*)d_in[4];
    const float* enc_W2   = (const float*)d_in[5];
    const float* enc_b2   = (const float*)d_in[6];
    const float* gat_W    = (const float*)d_in[7];
    const float* att_src  = (const float*)d_in[8];
    const float* att_dst  = (const float*)d_in[9];
    const float* gat_b    = (const float*)d_in[10];
    const float* ln_g     = (const float*)d_in[11];
    const float* ln_b     = (const float*)d_in[12];
    const float* head_W1  = (const float*)d_in[13];
    const float* head_b1  = (const float*)d_in[14];
    const float* head_W2  = (const float*)d_in[15];
    const float* head_b2  = (const float*)d_in[16];
    float* out = (float*)d_out;

    float* d_h  = nullptr; cudaGetSymbolAddress((void**)&d_h,  g_h);
    float* d_was = nullptr; cudaGetSymbolAddress((void**)&d_was, g_was);
    float* d_wad = nullptr; cudaGetSymbolAddress((void**)&d_wad, g_wad);
    float* d_as = nullptr; cudaGetSymbolAddress((void**)&d_as, g_as);
    float* d_ad = nullptr; cudaGetSymbolAddress((void**)&d_ad, g_ad);
    __nv_bfloat16 *d_ah, *d_al, *d_weh, *d_wel;
    __half *d_z, *d_wtf;
    cudaGetSymbolAddress((void**)&d_ah,  g_a_hi);
    cudaGetSymbolAddress((void**)&d_al,  g_a_lo);
    cudaGetSymbolAddress((void**)&d_z,   g_z);
    cudaGetSymbolAddress((void**)&d_wtf, g_wtf);
    cudaGetSymbolAddress((void**)&d_weh, g_wte_hi);
    cudaGetSymbolAddress((void**)&d_wel, g_wte_lo);

    static bool init_done = false;
    static cudaStream_t s2;
    static cudaEvent_t evFork, evJoin;
    if (!init_done) {
        cudaFuncSetAttribute(gemm_enc, cudaFuncAttributeMaxDynamicSharedMemorySize, ENC_SMEM);
        cudaFuncSetAttribute(gemm_lay, cudaFuncAttributeMaxDynamicSharedMemorySize, LAY_SMEM);
        cudaStreamCreateWithFlags(&s2, cudaStreamNonBlocking);
        cudaEventCreateWithFlags(&evFork, cudaEventDisableTiming);
        cudaEventCreateWithFlags(&evJoin, cudaEventDisableTiming);
        init_done = true;
    }

    // ---- fork: CSR build + layer weight prep on s2, encoder path on stream 0 ----
    cudaEventRecord(evFork, 0);
    cudaStreamWaitEvent(s2, evFork, 0);

    k_init_counts<<<(NN + 255) / 256, 256, 0, s2>>>();
    k_count<<<(EE + 255) / 256, 256, 0, s2>>>(ei + EE);
    k_scan1<<<SCAN_BLOCKS, 1024, 0, s2>>>();
    k_scan2<<<1, 64, 0, s2>>>();
    k_scan3<<<SCAN_BLOCKS, 1024, 0, s2>>>();
    k_scatter<<<(EP + 255) / 256, 256, 0, s2>>>(ei);
    k_wsplit_cat<<<(LL * HC * HID + 255) / 256, 256, 0, s2>>>(gat_W);

    k_wsplit<<<(HID * 128 + 255) / 256, 256>>>(enc_W2, d_weh, d_wel, HID);
    k_wattn<<<(LL * HC + 255) / 256, 256>>>(gat_W, att_src, att_dst);
    k_enc1<<<(NN * 32 + 255) / 256, 256>>>(x, enc_W1, enc_b1);
    gemm_enc<<<MT64, 256, ENC_SMEM>>>(d_ah, d_al, d_weh, d_wel,
                                      enc_b2, d_was, d_wad,
                                      d_h, d_as, d_ad, NN);

    cudaEventRecord(evJoin, s2);
    cudaStreamWaitEvent(0, evJoin, 0);

    // GAT layers
    for (int l = 0; l < LL; l++) {
        k_aggh<<<(NN + 7) / 8, 256>>>();
        const float* nw_s = (l + 1 < LL) ? d_was + (l + 1) * HC : nullptr;
        const float* nw_d = (l + 1 < LL) ? d_wad + (l + 1) * HC : nullptr;
        gemm_lay<<<MT64, 256, LAY_SMEM>>>(d_z,
                                          d_wtf + (size_t)l * HC * HID,
                                          gat_b + l * HID, ln_g + l * HID, ln_b + l * HID,
                                          nw_s, nw_d, d_h);
    }

    // head MLP
    k_head<<<(NHYP + 7) / 8, 256>>>(hyp, head_W1, head_b1, head_W2, head_b2, out);
    (void)in_sizes; (void)n_in; (void)out_size;
}

// round 16
// speedup vs baseline: 1.9950x; 1.0407x over previous
#include <cuda_runtime.h>
#include <cuda_bf16.h>
#include <cuda_fp16.h>
#include <math_constants.h>
#include <cstdint>

// Problem constants
#define NN      50000
#define NPAD    50048       // MT64 * 64
#define EE      400000
#define EP      450000      // E + N self loops
#define D_IN    6
#define HID     128
#define NH      4
#define HC      512         // NH * 128
#define LL      3
#define NHYP    4096
#define MT64    782         // ceil(NN/64)
#define SCAN_BLOCKS 49

// ---------------- device scratch (static, no allocation) ----------------
__device__ float g_h  [NN * HID];            // current node features (fp32, residual/head path)
__device__ __half g_hf[NN * HID];            // fp16 shadow of h (gather path)
__device__ __nv_bfloat16 g_a_hi[NPAD * HID]; // encoder GEMM A operand (bf16 split)
__device__ __nv_bfloat16 g_a_lo[NPAD * HID];
__device__ __half g_z[NPAD * HC];            // layer GEMM A operand (fp16)
__device__ float g_as [NN * NH];
__device__ float g_ad [NN * NH];
__device__ float g_was[LL * HC];
__device__ float g_wad[LL * HC];
__device__ int   g_cnt   [NN];
__device__ int   g_rowptr[NN + 1];
__device__ int   g_cursor[NN];
__device__ int   g_srcs  [EP];
__device__ int   g_bsum  [64];
__device__ __half g_wtf[LL * HC * HID];            // layer Wcat^T fp16: [l][c*512 + k]
__device__ __nv_bfloat16 g_wte_hi[HID * HID];      // encoder W2^T bf16 split [128,128]
__device__ __nv_bfloat16 g_wte_lo[HID * HID];

// ---------------- helpers ----------------
__device__ __forceinline__ uint32_t smem_u32(const void* p) {
    uint32_t a;
    asm("{ .reg .u64 t; cvta.to.shared.u64 t, %1; cvt.u32.u64 %0, t; }" : "=r"(a) : "l"(p));
    return a;
}
__device__ __forceinline__ void ldsm_x4(uint32_t& a0, uint32_t& a1, uint32_t& a2, uint32_t& a3, uint32_t addr) {
    asm volatile("ldmatrix.sync.aligned.m8n8.x4.shared.b16 {%0,%1,%2,%3}, [%4];"
                 : "=r"(a0), "=r"(a1), "=r"(a2), "=r"(a3) : "r"(addr));
}
__device__ __forceinline__ void mma_bf16(float* c, const uint32_t* a, uint32_t b0, uint32_t b1) {
    asm volatile("mma.sync.aligned.m16n8k16.row.col.f32.bf16.bf16.f32 "
                 "{%0,%1,%2,%3}, {%4,%5,%6,%7}, {%8,%9}, {%0,%1,%2,%3};"
                 : "+f"(c[0]), "+f"(c[1]), "+f"(c[2]), "+f"(c[3])
                 : "r"(a[0]), "r"(a[1]), "r"(a[2]), "r"(a[3]), "r"(b0), "r"(b1));
}
__device__ __forceinline__ void mma_f16(float* c, const uint32_t* a, uint32_t b0, uint32_t b1) {
    asm volatile("mma.sync.aligned.m16n8k16.row.col.f32.f16.f16.f32 "
                 "{%0,%1,%2,%3}, {%4,%5,%6,%7}, {%8,%9}, {%0,%1,%2,%3};"
                 : "+f"(c[0]), "+f"(c[1]), "+f"(c[2]), "+f"(c[3])
                 : "r"(a[0]), "r"(a[1]), "r"(a[2]), "r"(a[3]), "r"(b0), "r"(b1));
}
#define CP_ASYNC16(dst, src) asm volatile("cp.async.cg.shared.global [%0], [%1], 16;" :: "r"(dst), "l"(src))
#define CP_COMMIT()          asm volatile("cp.async.commit_group;" ::: "memory")
#define CP_WAIT0()           asm volatile("cp.async.wait_group 0;" ::: "memory")

__device__ __forceinline__ void split_bf16(float v, __nv_bfloat16& h, __nv_bfloat16& l) {
    h = __float2bfloat16(v);
    l = __float2bfloat16(v - __bfloat162float(h));
}

// smem layout constants (row pitch 272B = 136 16-bit elems)
#define ROWB  272
#define ATILE (64 * ROWB)            // 17408
#define BTILE (128 * ROWB)           // 34816
// encoder gemm (K=128, bf16 3-term): A hi/lo + B hi/lo
#define OFF_AHI 0
#define OFF_ALO ATILE
#define OFF_BHI (2 * ATILE)
#define OFF_BLO (2 * ATILE + BTILE)
#define ENC_SMEM (2 * ATILE + 2 * BTILE)   // 104448 -> 2 CTAs/SM
// layer gemm (K=512, fp16 1-term): A single + B single
#define OFF_LA  0
#define OFF_LB  ATILE
#define LAY_SMEM (ATILE + BTILE)           // 52224 -> 4 CTAs/SM
#define CS_STRIDE 133
// epilogue param offsets inside dynamic smem (cs region = 34048B)
#define EP_WAS  34048
#define EP_WAD  36096
#define EP_BIAS 38144
#define EP_LNG  38656
#define EP_LNB  39168
#define EP_MU   39680
#define EP_RSTD 39936

// ================= encoder tensor-core GEMM (K=128, bf16 3-term) + dots epilogue =================
__global__ __launch_bounds__(256) void gemm_enc(
        const __nv_bfloat16* __restrict__ A_hi, const __nv_bfloat16* __restrict__ A_lo,
        const __nv_bfloat16* __restrict__ Bt_hi, const __nv_bfloat16* __restrict__ Bt_lo,
        const float* __restrict__ bias,
        const float* __restrict__ was, const float* __restrict__ wad,
        float* __restrict__ Cout,
        float* __restrict__ as_out, float* __restrict__ ad_out, int M) {
    extern __shared__ char smem[];
    __shared__ float s_was[HC], s_wad[HC];
    __shared__ float s_bias[128];
    const uint32_t sb = smem_u32(smem);
    const int tid = threadIdx.x, wid = tid >> 5, lane = tid & 31;
    const int rowBase = blockIdx.x * 64;

    if (tid < 128) s_bias[tid] = bias[tid];
    for (int i = tid; i < HC; i += 256) { s_was[i] = was[i]; s_wad[i] = wad[i]; }

    const int wm = wid & 1, wn = wid >> 1;
    const int mW = wm * 32, nW = wn * 32;
    float acc[2][4][4];
    #pragma unroll
    for (int mi = 0; mi < 2; mi++)
        #pragma unroll
        for (int ni = 0; ni < 4; ni++)
            #pragma unroll
            for (int j = 0; j < 4; j++) acc[mi][ni][j] = 0.f;

    const int aRow  = (lane & 15);
    const int aColB = ((lane >> 4) & 1) * 16;
    const int bRow  = ((lane >> 4) & 1) * 8 + (lane & 7);
    const int bColB = ((lane >> 3) & 1) * 16;
    const uint32_t aHi = sb + OFF_AHI, aLo = sb + OFF_ALO;
    const uint32_t bHi = sb + OFF_BHI, bLo = sb + OFF_BLO;

    #pragma unroll
    for (int i = 0; i < 8; i++) {
        int li = tid + 256 * i;
        int row = li >> 4, c8 = (li & 15) * 8;
        size_t gidx = (size_t)row * HID + c8;
        uint32_t off = (uint32_t)row * ROWB + (uint32_t)c8 * 2;
        CP_ASYNC16(sb + OFF_BHI + off, &Bt_hi[gidx]);
        CP_ASYNC16(sb + OFF_BLO + off, &Bt_lo[gidx]);
    }
    #pragma unroll
    for (int i = 0; i < 4; i++) {
        int li = tid + 256 * i;
        int row = li >> 4, c8 = (li & 15) * 8;
        size_t gidx = (size_t)(rowBase + row) * HID + c8;
        uint32_t off = (uint32_t)row * ROWB + (uint32_t)c8 * 2;
        CP_ASYNC16(sb + OFF_AHI + off, &A_hi[gidx]);
        CP_ASYNC16(sb + OFF_ALO + off, &A_lo[gidx]);
    }
    CP_COMMIT();
    CP_WAIT0();
    __syncthreads();

    #pragma unroll
    for (int kb = 0; kb < 8; kb++) {
        const uint32_t kByte = kb * 32;
        uint32_t ah[2][4], al[2][4], bh[4][2], bl[4][2];
        #pragma unroll
        for (int mi = 0; mi < 2; mi++) {
            uint32_t ao = (uint32_t)(mW + mi * 16 + aRow) * ROWB + kByte + aColB;
            ldsm_x4(ah[mi][0], ah[mi][1], ah[mi][2], ah[mi][3], aHi + ao);
            ldsm_x4(al[mi][0], al[mi][1], al[mi][2], al[mi][3], aLo + ao);
        }
        #pragma unroll
        for (int nj = 0; nj < 2; nj++) {
            uint32_t bo = (uint32_t)(nW + nj * 16 + bRow) * ROWB + kByte + bColB;
            ldsm_x4(bh[nj*2][0], bh[nj*2][1], bh[nj*2+1][0], bh[nj*2+1][1], bHi + bo);
            ldsm_x4(bl[nj*2][0], bl[nj*2][1], bl[nj*2+1][0], bl[nj*2+1][1], bLo + bo);
        }
        #pragma unroll
        for (int mi = 0; mi < 2; mi++)
            #pragma unroll
            for (int ni = 0; ni < 4; ni++) {
                mma_bf16(acc[mi][ni], ah[mi], bh[ni][0], bh[ni][1]);
                mma_bf16(acc[mi][ni], ah[mi], bl[ni][0], bl[ni][1]);
                mma_bf16(acc[mi][ni], al[mi], bh[ni][0], bh[ni][1]);
            }
    }
    __syncthreads();

    float* cs = (float*)smem;
    {
        const int r0 = (lane >> 2), c0 = (lane & 3) * 2;
        #pragma unroll
        for (int mi = 0; mi < 2; mi++)
            #pragma unroll
            for (int ni = 0; ni < 4; ni++) {
                int rr = mW + mi * 16 + r0;
                int cc = nW + ni * 8 + c0;
                cs[rr * CS_STRIDE + cc]           = acc[mi][ni][0];
                cs[rr * CS_STRIDE + cc + 1]       = acc[mi][ni][1];
                cs[(rr + 8) * CS_STRIDE + cc]     = acc[mi][ni][2];
                cs[(rr + 8) * CS_STRIDE + cc + 1] = acc[mi][ni][3];
            }
    }
    __syncthreads();

    #pragma unroll
    for (int i = 0; i < 8; i++) {
        int li = tid + 256 * i;
        int row = li >> 5, c4 = (li & 31) * 4;
        int gr = rowBase + row;
        float y0 = cs[row * CS_STRIDE + c4 + 0] + s_bias[c4 + 0];
        float y1 = cs[row * CS_STRIDE + c4 + 1] + s_bias[c4 + 1];
        float y2 = cs[row * CS_STRIDE + c4 + 2] + s_bias[c4 + 2];
        float y3 = cs[row * CS_STRIDE + c4 + 3] + s_bias[c4 + 3];
        cs[row * CS_STRIDE + c4 + 0] = y0;
        cs[row * CS_STRIDE + c4 + 1] = y1;
        cs[row * CS_STRIDE + c4 + 2] = y2;
        cs[row * CS_STRIDE + c4 + 3] = y3;
        if (gr < M) {
            *(float4*)&Cout[(size_t)gr * HID + c4] = make_float4(y0, y1, y2, y3);
            __half hf[4] = {__float2half(y0), __float2half(y1), __float2half(y2), __float2half(y3)};
            *(uint2*)&g_hf[(size_t)gr * HID + c4] = *(uint2*)hf;
        }
    }
    __syncthreads();

    if (tid < 128) {
        int row = tid >> 1, cb = (tid & 1) * 64;
        int gr = rowBase + row;
        float as[4] = {0, 0, 0, 0}, ad[4] = {0, 0, 0, 0};
        const float* cr = cs + row * CS_STRIDE;
        #pragma unroll 4
        for (int c = cb; c < cb + 64; c++) {
            float y = cr[c];
            #pragma unroll
            for (int h = 0; h < 4; h++) {
                as[h] += y * s_was[h * 128 + c];
                ad[h] += y * s_wad[h * 128 + c];
            }
        }
        #pragma unroll
        for (int h = 0; h < 4; h++) {
            as[h] += __shfl_down_sync(0xFFFFFFFF, as[h], 1);
            ad[h] += __shfl_down_sync(0xFFFFFFFF, ad[h], 1);
        }
        if (((tid & 1) == 0) && gr < M) {
            #pragma unroll
            for (int h = 0; h < 4; h++) {
                as_out[gr * 4 + h] = as[h];
                ad_out[gr * 4 + h] = ad[h];
            }
        }
    }
}

// ================= layer tensor-core GEMM (K=512, fp16 1-term) + fused epilogue =================
__global__ __launch_bounds__(256) void gemm_lay(
        const __half* __restrict__ Z,
        const __half* __restrict__ Btf,
        const float* __restrict__ bias,
        const float* __restrict__ lng, const float* __restrict__ lnb,
        const float* __restrict__ was, const float* __restrict__ wad,
        float* __restrict__ Cout) {
    extern __shared__ char smem[];
    const uint32_t sb = smem_u32(smem);
    const int tid = threadIdx.x, wid = tid >> 5, lane = tid & 31;
    const int rowBase = blockIdx.x * 64;
    const bool dots = (was != nullptr);

    const int wm = wid & 1, wn = wid >> 1;
    const int mW = wm * 32, nW = wn * 32;
    float acc[2][4][4];
    #pragma unroll
    for (int mi = 0; mi < 2; mi++)
        #pragma unroll
        for (int ni = 0; ni < 4; ni++)
            #pragma unroll
            for (int j = 0; j < 4; j++) acc[mi][ni][j] = 0.f;

    const int aRow  = (lane & 15);
    const int aColB = ((lane >> 4) & 1) * 16;
    const int bRow  = ((lane >> 4) & 1) * 8 + (lane & 7);
    const int bColB = ((lane >> 3) & 1) * 16;
    const uint32_t aB = sb + OFF_LA;
    const uint32_t bB = sb + OFF_LB;

    for (int ch = 0; ch < 4; ch++) {
        const int kOff = ch * 128;
        #pragma unroll
        for (int i = 0; i < 8; i++) {
            int li = tid + 256 * i;
            int row = li >> 4, c8 = (li & 15) * 8;
            size_t gidx = (size_t)row * HC + kOff + c8;
            uint32_t off = (uint32_t)row * ROWB + (uint32_t)c8 * 2;
            CP_ASYNC16(bB + off, &Btf[gidx]);
        }
        #pragma unroll
        for (int i = 0; i < 4; i++) {
            int li = tid + 256 * i;
            int row = li >> 4, c8 = (li & 15) * 8;
            size_t gidx = (size_t)(rowBase + row) * HC + kOff + c8;
            uint32_t off = (uint32_t)row * ROWB + (uint32_t)c8 * 2;
            CP_ASYNC16(aB + off, &Z[gidx]);
        }
        CP_COMMIT();
        CP_WAIT0();
        __syncthreads();

        #pragma unroll
        for (int kb = 0; kb < 8; kb++) {
            const uint32_t kByte = kb * 32;
            uint32_t ah[2][4], bb[4][2];
            #pragma unroll
            for (int mi = 0; mi < 2; mi++) {
                uint32_t ao = (uint32_t)(mW + mi * 16 + aRow) * ROWB + kByte + aColB;
                ldsm_x4(ah[mi][0], ah[mi][1], ah[mi][2], ah[mi][3], aB + ao);
            }
            #pragma unroll
            for (int nj = 0; nj < 2; nj++) {
                uint32_t bo = (uint32_t)(nW + nj * 16 + bRow) * ROWB + kByte + bColB;
                ldsm_x4(bb[nj*2][0], bb[nj*2][1], bb[nj*2+1][0], bb[nj*2+1][1], bB + bo);
            }
            #pragma unroll
            for (int mi = 0; mi < 2; mi++)
                #pragma unroll
                for (int ni = 0; ni < 4; ni++)
                    mma_f16(acc[mi][ni], ah[mi], bb[ni][0], bb[ni][1]);
        }
        __syncthreads();
    }

    // --- epilogue ---
    float* cs     = (float*)smem;
    float* p_was  = (float*)(smem + EP_WAS);
    float* p_wad  = (float*)(smem + EP_WAD);
    float* p_bias = (float*)(smem + EP_BIAS);
    float* p_lng  = (float*)(smem + EP_LNG);
    float* p_lnb  = (float*)(smem + EP_LNB);
    float* p_mu   = (float*)(smem + EP_MU);
    float* p_rstd = (float*)(smem + EP_RSTD);

    {
        const int r0 = (lane >> 2), c0 = (lane & 3) * 2;
        #pragma unroll
        for (int mi = 0; mi < 2; mi++)
            #pragma unroll
            for (int ni = 0; ni < 4; ni++) {
                int rr = mW + mi * 16 + r0;
                int cc = nW + ni * 8 + c0;
                cs[rr * CS_STRIDE + cc]           = acc[mi][ni][0];
                cs[rr * CS_STRIDE + cc + 1]       = acc[mi][ni][1];
                cs[(rr + 8) * CS_STRIDE + cc]     = acc[mi][ni][2];
                cs[(rr + 8) * CS_STRIDE + cc + 1] = acc[mi][ni][3];
            }
    }
    if (tid < 128) { p_bias[tid] = bias[tid]; p_lng[tid] = lng[tid]; p_lnb[tid] = lnb[tid]; }
    if (dots)
        for (int i = tid; i < HC; i += 256) { p_was[i] = was[i]; p_wad[i] = wad[i]; }
    __syncthreads();

    #pragma unroll
    for (int i = 0; i < 8; i++) {
        int li = tid + 256 * i;
        int row = li >> 5, c4 = (li & 31) * 4;
        #pragma unroll
        for (int j = 0; j < 4; j++)
            cs[row * CS_STRIDE + c4 + j] = 0.25f * cs[row * CS_STRIDE + c4 + j] + p_bias[c4 + j];
    }
    __syncthreads();
    if (tid < 64) {
        const float* cr = cs + tid * CS_STRIDE;
        float sum = 0.f;
        #pragma unroll 8
        for (int c = 0; c < 128; c++) sum += cr[c];
        float mu = sum * (1.0f / 128.0f);
        float var = 0.f;
        #pragma unroll 8
        for (int c = 0; c < 128; c++) { float d = cr[c] - mu; var += d * d; }
        p_mu[tid] = mu;
        p_rstd[tid] = rsqrtf(var * (1.0f / 128.0f) + 1e-5f);
    }
    __syncthreads();
    #pragma unroll
    for (int i = 0; i < 8; i++) {
        int li = tid + 256 * i;
        int row = li >> 5, c4 = (li & 31) * 4;
        int gr = rowBase + row;
        float mu = p_mu[row], rs = p_rstd[row];
        float y[4];
        #pragma unroll
        for (int j = 0; j < 4; j++) {
            float v = (cs[row * CS_STRIDE + c4 + j] - mu) * rs * p_lng[c4 + j] + p_lnb[c4 + j];
            y[j] = fmaxf(v, 0.f);
        }
        if (gr < NN) {
            float4 res = *(const float4*)&Cout[(size_t)gr * HID + c4];
            float4 o = make_float4(y[0] + res.x, y[1] + res.y, y[2] + res.z, y[3] + res.w);
            *(float4*)&Cout[(size_t)gr * HID + c4] = o;
            __half hf[4] = {__float2half(o.x), __float2half(o.y), __float2half(o.z), __float2half(o.w)};
            *(uint2*)&g_hf[(size_t)gr * HID + c4] = *(uint2*)hf;
            cs[row * CS_STRIDE + c4 + 0] = o.x;
            cs[row * CS_STRIDE + c4 + 1] = o.y;
            cs[row * CS_STRIDE + c4 + 2] = o.z;
            cs[row * CS_STRIDE + c4 + 3] = o.w;
        }
    }
    __syncthreads();

    if (dots && tid < 128) {
        int row = tid >> 1, cb = (tid & 1) * 64;
        int gr = rowBase + row;
        float as[4] = {0, 0, 0, 0}, ad[4] = {0, 0, 0, 0};
        const float* cr = cs + row * CS_STRIDE;
        #pragma unroll 4
        for (int c = cb; c < cb + 64; c++) {
            float y = cr[c];
            #pragma unroll
            for (int h = 0; h < 4; h++) {
                as[h] += y * p_was[h * 128 + c];
                ad[h] += y * p_wad[h * 128 + c];
            }
        }
        #pragma unroll
        for (int h = 0; h < 4; h++) {
            as[h] += __shfl_down_sync(0xFFFFFFFF, as[h], 1);
            ad[h] += __shfl_down_sync(0xFFFFFFFF, ad[h], 1);
        }
        if (((tid & 1) == 0) && gr < NN) {
            #pragma unroll
            for (int h = 0; h < 4; h++) {
                g_as[gr * 4 + h] = as[h];
                g_ad[gr * 4 + h] = ad[h];
            }
        }
    }
}

// ---------------- encoder W2 transpose+split (bf16) ----------------
__global__ void k_wsplit(const float* __restrict__ W, __nv_bfloat16* __restrict__ hi,
                         __nv_bfloat16* __restrict__ lo, int NC) {
    int idx = blockIdx.x * blockDim.x + threadIdx.x;
    if (idx >= NC * 128) return;
    int n = idx >> 7, k = idx & 127;
    float x = W[k * NC + n];
    split_bf16(x, hi[idx], lo[idx]);
}

// ---------------- layer Wcat^T -> fp16 ----------------
__global__ void k_wsplit_cat(const float* __restrict__ gat_W) {
    int idx = blockIdx.x * blockDim.x + threadIdx.x;
    if (idx >= LL * HC * HID) return;
    int l = idx >> 16;
    int r = idx & 65535;
    int c = r >> 9;
    int k = r & 511;
    int j = k & 127, hh = k >> 7;
    float x = gat_W[(size_t)l * 65536 + j * 512 + hh * 128 + c];
    g_wtf[idx] = __float2half(x);
}

// ---------------- attn weight vectors ----------------
__global__ void k_wattn(const float* __restrict__ gat_W,
                        const float* __restrict__ att_src, const float* __restrict__ att_dst) {
    int idx = blockIdx.x * blockDim.x + threadIdx.x;
    if (idx >= LL * HC) return;
    int l = idx >> 9;
    int r = idx & 511;
    int hh = r >> 7, j = r & 127;
    const float* wr = gat_W + (size_t)l * 65536 + j * 512 + hh * 128;
    const float* as = att_src + l * HC + hh * 128;
    const float* ad = att_dst + l * HC + hh * 128;
    float sa = 0.f, sd = 0.f;
    #pragma unroll 8
    for (int c = 0; c < 128; c++) { sa += wr[c] * as[c]; sd += wr[c] * ad[c]; }
    g_was[idx] = sa;
    g_wad[idx] = sd;
}

// ---------------- CSR build ----------------
__global__ void k_init_counts() {
    int n = blockIdx.x * blockDim.x + threadIdx.x;
    if (n < NN) g_cnt[n] = 1;
}
__global__ void k_count(const int* __restrict__ dst) {
    int e = blockIdx.x * blockDim.x + threadIdx.x;
    if (e < EE) atomicAdd(&g_cnt[dst[e]], 1);
}
__global__ void k_scan1() {
    __shared__ int s[1024];
    int t = threadIdx.x;
    int i = blockIdx.x * 1024 + t;
    int v = (i < NN) ? g_cnt[i] : 0;
    s[t] = v;
    __syncthreads();
    #pragma unroll
    for (int off = 1; off < 1024; off <<= 1) {
        int x = (t >= off) ? s[t - off] : 0;
        __syncthreads();
        s[t] += x;
        __syncthreads();
    }
    if (i < NN) g_rowptr[i + 1] = s[t];
    if (t == 1023) g_bsum[blockIdx.x] = s[1023];
}
__global__ void k_scan2() {
    __shared__ int s[64];
    int t = threadIdx.x;
    int v = (t < SCAN_BLOCKS) ? g_bsum[t] : 0;
    s[t] = v;
    __syncthreads();
    #pragma unroll
    for (int off = 1; off < 64; off <<= 1) {
        int x = (t >= off) ? s[t - off] : 0;
        __syncthreads();
        s[t] += x;
        __syncthreads();
    }
    if (t < SCAN_BLOCKS) g_bsum[t] = s[t] - v;   // exclusive
}
__global__ void k_scan3() {
    int t = threadIdx.x;
    int i = blockIdx.x * 1024 + t;
    if (i < NN) {
        int v = g_rowptr[i + 1] + g_bsum[blockIdx.x];
        g_rowptr[i + 1] = v;
        if (i + 1 < NN) g_cursor[i + 1] = v;
    }
    if (i == 0) { g_rowptr[0] = 0; g_cursor[0] = 0; }
}
__global__ void k_scatter(const int* __restrict__ ei) {
    int e = blockIdx.x * blockDim.x + threadIdx.x;
    if (e >= EP) return;
    int s, d;
    if (e < EE) { s = ei[e]; d = ei[EE + e]; }
    else        { s = e - EE; d = s; }
    int pos = atomicAdd(&g_cursor[d], 1);
    g_srcs[pos] = s;
}

// ---------------- encoder first layer (K=6), W1 in smem, writes bf16 split ----------------
__global__ __launch_bounds__(256) void k_enc1(const float* __restrict__ x,
                                              const float* __restrict__ W1,
                                              const float* __restrict__ b1) {
    __shared__ float sW[D_IN * HID], sB[HID];
    int tid = threadIdx.x;
    for (int i = tid; i < D_IN * HID; i += 256) sW[i] = W1[i];
    if (tid < HID) sB[tid] = b1[tid];
    __syncthreads();

    int gid = blockIdx.x * 256 + tid;
    if (gid >= NN * 32) return;
    int n = gid >> 5, c4 = (gid & 31) * 4;
    const float* xr = x + n * D_IN;
    float xv[D_IN];
    #pragma unroll
    for (int k = 0; k < D_IN; k++) xv[k] = xr[k];
    __nv_bfloat16 hi[4], lo[4];
    #pragma unroll
    for (int j = 0; j < 4; j++) {
        int c = c4 + j;
        float acc = sB[c];
        #pragma unroll
        for (int k = 0; k < D_IN; k++) acc += xv[k] * sW[k * HID + c];
        split_bf16(fmaxf(acc, 0.0f), hi[j], lo[j]);
    }
    *(uint2*)&g_a_hi[(size_t)n * HID + c4] = *(uint2*)hi;
    *(uint2*)&g_a_lo[(size_t)n * HID + c4] = *(uint2*)lo;
}

// ---------------- h-space aggregation, single-pass softmax (fp16 h gather) -> fp16 z ----------------
__global__ __launch_bounds__(256) void k_aggh() {
    int warp = threadIdx.x >> 5, lane = threadIdx.x & 31;
    int n = blockIdx.x * 8 + warp;
    if (n >= NN) return;
    int r0 = g_rowptr[n], r1 = g_rowptr[n + 1];

    float4 adv = *(const float4*)&g_ad[n * 4];
    float adh[4] = {adv.x, adv.y, adv.z, adv.w};

    // single pass: alpha_h = exp(e) (unnormalized); e bounded O(1), clamp for safety
    float denom[4] = {0, 0, 0, 0};
    float z[4][4];
    #pragma unroll
    for (int h = 0; h < 4; h++)
        #pragma unroll
        for (int i = 0; i < 4; i++) z[h][i] = 0.f;

    for (int idx = r0; idx < r1; idx++) {
        int s = g_srcs[idx];
        float4 asv = *(const float4*)&g_as[s * 4];
        float ex[4];
        {
            float e;
            e = asv.x + adh[0]; e = e > 0 ? e : 0.2f * e; ex[0] = __expf(fminf(e, 60.f));
            e = asv.y + adh[1]; e = e > 0 ? e : 0.2f * e; ex[1] = __expf(fminf(e, 60.f));
            e = asv.z + adh[2]; e = e > 0 ? e : 0.2f * e; ex[2] = __expf(fminf(e, 60.f));
            e = asv.w + adh[3]; e = e > 0 ? e : 0.2f * e; ex[3] = __expf(fminf(e, 60.f));
        }
        denom[0] += ex[0]; denom[1] += ex[1]; denom[2] += ex[2]; denom[3] += ex[3];
        uint2 hv2 = *(const uint2*)&g_hf[(size_t)s * HID + lane * 4];
        float2 f01 = __half22float2(*(__half2*)&hv2.x);
        float2 f23 = __half22float2(*(__half2*)&hv2.y);
        #pragma unroll
        for (int h = 0; h < 4; h++) {
            z[h][0] += ex[h] * f01.x;
            z[h][1] += ex[h] * f01.y;
            z[h][2] += ex[h] * f23.x;
            z[h][3] += ex[h] * f23.y;
        }
    }

    #pragma unroll
    for (int h = 0; h < 4; h++) {
        float inv = 1.0f / (denom[h] + 1e-16f);
        __half zz[4];
        #pragma unroll
        for (int i = 0; i < 4; i++) zz[i] = __float2half(z[h][i] * inv);
        size_t o = (size_t)n * HC + h * 128 + lane * 4;
        *(uint2*)&g_z[o] = *(uint2*)zz;
    }
}

// ---------------- head MLP ----------------
__global__ __launch_bounds__(256) void k_head(const int* __restrict__ hyp,
                                              const float* __restrict__ W1,
                                              const float* __restrict__ b1,
                                              const float* __restrict__ W2,
                                              const float* __restrict__ b2,
                                              float* __restrict__ out) {
    int warp = threadIdx.x >> 5, lane = threadIdx.x & 31;
    int i = blockIdx.x * 8 + warp;
    if (i >= NHYP) return;
    int idx = hyp[i];
    const float* hr = g_h + (size_t)idx * HID;
    float a0 = b1[lane], a1 = b1[lane + 32];
    for (int c = 0; c < HID; c++) {
        float hv = hr[c];
        a0 += hv * W1[c * 64 + lane];
        a1 += hv * W1[c * 64 + lane + 32];
    }
    a0 = fmaxf(a0, 0.0f);
    a1 = fmaxf(a1, 0.0f);
    float p = a0 * W2[lane] + a1 * W2[lane + 32];
    #pragma unroll
    for (int off = 16; off; off >>= 1) p += __shfl_xor_sync(0xFFFFFFFF, p, off);
    if (lane == 0) out[i] = p + b2[0];
}

// ---------------- launch ----------------
extern "C" void kernel_launch(void* const* d_in, const int* in_sizes, int n_in,
                              void* d_out, int out_size) {
    const float* x        = (const float*)d_in[0];
    const int*   ei       = (const int*)  d_in[1];
    const int*   hyp      = (const int*)  d_in[2];
    const float* enc_W1   = (const float*)d_in[3];
    const float* enc_b1   = (const float*)d_in[4];
    const float* enc_W2   = (const float*)d_in[5];
    const float* enc_b2   = (const float*)d_in[6];
    const float* gat_W    = (const float*)d_in[7];
    const float* att_src  = (const float*)d_in[8];
    const float* att_dst  = (const float*)d_in[9];
    const float* gat_b    = (const float*)d_in[10];
    const float* ln_g     = (const float*)d_in[11];
    const float* ln_b     = (const float*)d_in[12];
    const float* head_W1  = (const float*)d_in[13];
    const float* head_b1  = (const float*)d_in[14];
    const float* head_W2  = (const float*)d_in[15];
    const float* head_b2  = (const float*)d_in[16];
    float* out = (float*)d_out;

    float* d_h  = nullptr; cudaGetSymbolAddress((void**)&d_h,  g_h);
    float* d_was = nullptr; cudaGetSymbolAddress((void**)&d_was, g_was);
    float* d_wad = nullptr; cudaGetSymbolAddress((void**)&d_wad, g_wad);
    float* d_as = nullptr; cudaGetSymbolAddress((void**)&d_as, g_as);
    float* d_ad = nullptr; cudaGetSymbolAddress((void**)&d_ad, g_ad);
    __nv_bfloat16 *d_ah, *d_al, *d_weh, *d_wel;
    __half *d_z, *d_wtf;
    cudaGetSymbolAddress((void**)&d_ah,  g_a_hi);
    cudaGetSymbolAddress((void**)&d_al,  g_a_lo);
    cudaGetSymbolAddress((void**)&d_z,   g_z);
    cudaGetSymbolAddress((void**)&d_wtf, g_wtf);
    cudaGetSymbolAddress((void**)&d_weh, g_wte_hi);
    cudaGetSymbolAddress((void**)&d_wel, g_wte_lo);

    static bool init_done = false;
    static cudaStream_t s2;
    static cudaEvent_t evFork, evJoin;
    if (!init_done) {
        cudaFuncSetAttribute(gemm_enc, cudaFuncAttributeMaxDynamicSharedMemorySize, ENC_SMEM);
        cudaFuncSetAttribute(gemm_lay, cudaFuncAttributeMaxDynamicSharedMemorySize, LAY_SMEM);
        cudaStreamCreateWithFlags(&s2, cudaStreamNonBlocking);
        cudaEventCreateWithFlags(&evFork, cudaEventDisableTiming);
        cudaEventCreateWithFlags(&evJoin, cudaEventDisableTiming);
        init_done = true;
    }

    // ---- fork: CSR build + layer weight prep on s2, encoder path on stream 0 ----
    cudaEventRecord(evFork, 0);
    cudaStreamWaitEvent(s2, evFork, 0);

    k_init_counts<<<(NN + 255) / 256, 256, 0, s2>>>();
    k_count<<<(EE + 255) / 256, 256, 0, s2>>>(ei + EE);
    k_scan1<<<SCAN_BLOCKS, 1024, 0, s2>>>();
    k_scan2<<<1, 64, 0, s2>>>();
    k_scan3<<<SCAN_BLOCKS, 1024, 0, s2>>>();
    k_scatter<<<(EP + 255) / 256, 256, 0, s2>>>(ei);
    k_wsplit_cat<<<(LL * HC * HID + 255) / 256, 256, 0, s2>>>(gat_W);

    k_wsplit<<<(HID * 128 + 255) / 256, 256>>>(enc_W2, d_weh, d_wel, HID);
    k_wattn<<<(LL * HC + 255) / 256, 256>>>(gat_W, att_src, att_dst);
    k_enc1<<<(NN * 32 + 255) / 256, 256>>>(x, enc_W1, enc_b1);
    gemm_enc<<<MT64, 256, ENC_SMEM>>>(d_ah, d_al, d_weh, d_wel,
                                      enc_b2, d_was, d_wad,
                                      d_h, d_as, d_ad, NN);

    cudaEventRecord(evJoin, s2);
    cudaStreamWaitEvent(0, evJoin, 0);

    // GAT layers
    for (int l = 0; l < LL; l++) {
        k_aggh<<<(NN + 7) / 8, 256>>>();
        const float* nw_s = (l + 1 < LL) ? d_was + (l + 1) * HC : nullptr;
        const float* nw_d = (l + 1 < LL) ? d_wad + (l + 1) * HC : nullptr;
        gemm_lay<<<MT64, 256, LAY_SMEM>>>(d_z,
                                          d_wtf + (size_t)l * HC * HID,
                                          gat_b + l * HID, ln_g + l * HID, ln_b + l * HID,
                                          nw_s, nw_d, d_h);
    }

    // head MLP
    k_head<<<(NHYP + 7) / 8, 256>>>(hyp, head_W1, head_b1, head_W2, head_b2, out);
    (void)in_sizes; (void)n_in; (void)out_size;
}